// round 1
// baseline (speedup 1.0000x reference)
#include <cuda_runtime.h>
#include <math.h>

// Problem constants: B=16, N=1024, D=768
#define NB   16
#define NN   1024
#define DD   768
#define MM   (NB * NN)   // 16384 rows

// ---------------- scratch (static device globals; no allocation) ----------------
__device__ float g_fp[(size_t)MM * DD];   // feat_proj   48MB
__device__ float g_y [(size_t)MM * DD];   // attention out
__device__ float g_u [(size_t)MM * DD];   // update gate u
__device__ float g_rx[(size_t)MM * DD];   // r * inputs
__device__ float g_q [MM];
__device__ float g_k [MM];

// ---------------- generic dual-operand SGEMM ----------------
// C[m,n] = sum_k A?[m,k] * W?[n,k]  (+ biases, + fused epilogue)
// K total = 768 (A1/W1 only) or 1536 (k<768 -> A1/W1, else A2/W2).
// M=16384, N=768 fixed; BM=BN=128, BK=8, 256 threads, 8x8 per thread.
// modes: 0 = store v (+b1)           (feat_proj)
//        1 = sigmoid(v+b1+b2)        (u)
//        2 = sigmoid(v+b1+b2)*X      (rx = r*inputs)
//        3 = out = (1-U)*X + U*tanh(v+b1+b2)   (final)
__global__ __launch_bounds__(256) void gemm_dual(
    const float* __restrict__ A1, const float* __restrict__ W1,
    const float* __restrict__ A2, const float* __restrict__ W2,
    const float* __restrict__ b1, const float* __restrict__ b2,
    const float* __restrict__ X,  const float* __restrict__ U,
    float* __restrict__ out, int K, int mode)
{
    __shared__ float As[8][128];
    __shared__ float Bs[8][128];

    const int tid = threadIdx.x;
    const int tx  = tid & 15;          // 0..15 -> 8 cols each
    const int ty  = tid >> 4;          // 0..15 -> 8 rows each
    const int m0  = blockIdx.y * 128;
    const int n0  = blockIdx.x * 128;

    const int li = tid >> 1;           // 0..127 (row of tile to load)
    const int lj = (tid & 1) * 4;      // 0 or 4 (k offset)

    float acc[8][8];
#pragma unroll
    for (int i = 0; i < 8; i++)
#pragma unroll
        for (int j = 0; j < 8; j++) acc[i][j] = 0.0f;

    for (int kb = 0; kb < K; kb += 8) {
        const float* Ap; const float* Wp; int ko;
        if (kb < DD) { Ap = A1; Wp = W1; ko = kb; }
        else         { Ap = A2; Wp = W2; ko = kb - DD; }

        float4 av = *(const float4*)(Ap + (size_t)(m0 + li) * DD + ko + lj);
        float4 wv = *(const float4*)(Wp + (size_t)(n0 + li) * DD + ko + lj);
        As[lj + 0][li] = av.x; As[lj + 1][li] = av.y;
        As[lj + 2][li] = av.z; As[lj + 3][li] = av.w;
        Bs[lj + 0][li] = wv.x; Bs[lj + 1][li] = wv.y;
        Bs[lj + 2][li] = wv.z; Bs[lj + 3][li] = wv.w;
        __syncthreads();

#pragma unroll
        for (int kk = 0; kk < 8; kk++) {
            float4 a0 = *(const float4*)&As[kk][ty * 8];
            float4 a1 = *(const float4*)&As[kk][ty * 8 + 4];
            float4 c0 = *(const float4*)&Bs[kk][tx * 8];
            float4 c1 = *(const float4*)&Bs[kk][tx * 8 + 4];
            float ar[8] = {a0.x, a0.y, a0.z, a0.w, a1.x, a1.y, a1.z, a1.w};
            float br[8] = {c0.x, c0.y, c0.z, c0.w, c1.x, c1.y, c1.z, c1.w};
#pragma unroll
            for (int i = 0; i < 8; i++)
#pragma unroll
                for (int j = 0; j < 8; j++)
                    acc[i][j] = fmaf(ar[i], br[j], acc[i][j]);
        }
        __syncthreads();
    }

    // epilogue
    float bsum[8];
#pragma unroll
    for (int j = 0; j < 8; j++) {
        int n = n0 + tx * 8 + j;
        bsum[j] = b1[n] + (b2 ? b2[n] : 0.0f);
    }

#pragma unroll
    for (int i = 0; i < 8; i++) {
        int m = m0 + ty * 8 + i;
        size_t ro = (size_t)m * DD;
#pragma unroll
        for (int j = 0; j < 8; j++) {
            int n = n0 + tx * 8 + j;
            float v = acc[i][j] + bsum[j];
            float o;
            if (mode == 0) {
                o = v;
            } else if (mode == 1) {
                o = 1.0f / (1.0f + expf(-v));
            } else if (mode == 2) {
                o = (1.0f / (1.0f + expf(-v))) * X[ro + n];
            } else {
                float uu = U[ro + n];
                float xv = X[ro + n];
                o = (1.0f - uu) * xv + uu * tanhf(v);
            }
            out[ro + n] = o;
        }
    }
}

// ---------------- q/k per-row dots ----------------
__global__ __launch_bounds__(256) void qk_kernel(
    const float* __restrict__ wq, const float* __restrict__ bq,
    const float* __restrict__ wk, const float* __restrict__ bk)
{
    const int m = blockIdx.x;
    const float* row = g_fp + (size_t)m * DD;
    const int tid = threadIdx.x;

    float sq = 0.0f, sk = 0.0f;
    for (int d = tid; d < DD; d += 256) {
        float v = row[d];
        sq = fmaf(v, wq[d], sq);
        sk = fmaf(v, wk[d], sk);
    }
#pragma unroll
    for (int o = 16; o; o >>= 1) {
        sq += __shfl_down_sync(0xFFFFFFFFu, sq, o);
        sk += __shfl_down_sync(0xFFFFFFFFu, sk, o);
    }
    __shared__ float rq[8], rk[8];
    if ((tid & 31) == 0) { rq[tid >> 5] = sq; rk[tid >> 5] = sk; }
    __syncthreads();
    if (tid == 0) {
        float a = 0.0f, c = 0.0f;
#pragma unroll
        for (int w = 0; w < 8; w++) { a += rq[w]; c += rk[w]; }
        g_q[m] = a + bq[0];
        g_k[m] = c + bk[0];
    }
}

// ---------------- fused attention: y = softmax-masked(A) @ feat_proj ----------------
// A[i,j] = adj ? exp(lrelu(q_i + k_j)) : 0 ; y normalized by row sum Z.
__global__ __launch_bounds__(256) void attn_kernel(const float* __restrict__ adj)
{
    __shared__ float As[8][128];
    __shared__ float Bs[8][128];
    __shared__ float sZ[128];

    const int b  = blockIdx.z;
    const int i0 = blockIdx.y * 128;
    const int d0 = blockIdx.x * 128;

    const int tid = threadIdx.x;
    const int tx  = tid & 15;
    const int ty  = tid >> 4;

    const float* adjB = adj + ((size_t)b * NN + i0) * NN;
    const float* fpB  = g_fp + (size_t)b * NN * DD;
    const float* qB   = g_q + b * NN + i0;
    const float* kB   = g_k + b * NN;

    const int ai = tid >> 1;            // 0..127: A-tile row
    const int aj = (tid & 1) * 4;       // 0/4:    A-tile k offset
    const int bj = tid >> 5;            // 0..7:   B-tile row (k)
    const int bn = (tid & 31) * 4;      // B-tile col

    const float qi = qB[ai];

    float acc[8][8];
    float zacc[8];
#pragma unroll
    for (int i = 0; i < 8; i++) {
        zacc[i] = 0.0f;
#pragma unroll
        for (int j = 0; j < 8; j++) acc[i][j] = 0.0f;
    }

    for (int jt = 0; jt < NN; jt += 8) {
        // generate A tile from adjacency + q/k
        {
            float4 av = *(const float4*)&adjB[(size_t)ai * NN + jt + aj];
            float4 kv = *(const float4*)&kB[jt + aj];
            float vr[4] = {qi + kv.x, qi + kv.y, qi + kv.z, qi + kv.w};
            float ad[4] = {av.x, av.y, av.z, av.w};
#pragma unroll
            for (int u2 = 0; u2 < 4; u2++) {
                float v = vr[u2];
                float lr = v >= 0.0f ? v : 0.01f * v;
                As[aj + u2][ai] = (ad[u2] > 0.5f) ? expf(lr) : 0.0f;
            }
        }
        // load feat_proj tile (already k-major: rows j, cols d)
        *(float4*)&Bs[bj][bn] = *(const float4*)&fpB[(size_t)(jt + bj) * DD + d0 + bn];
        __syncthreads();

#pragma unroll
        for (int kk = 0; kk < 8; kk++) {
            float4 a0 = *(const float4*)&As[kk][ty * 8];
            float4 a1 = *(const float4*)&As[kk][ty * 8 + 4];
            float4 c0 = *(const float4*)&Bs[kk][tx * 8];
            float4 c1 = *(const float4*)&Bs[kk][tx * 8 + 4];
            float ar[8] = {a0.x, a0.y, a0.z, a0.w, a1.x, a1.y, a1.z, a1.w};
            float br[8] = {c0.x, c0.y, c0.z, c0.w, c1.x, c1.y, c1.z, c1.w};
#pragma unroll
            for (int i = 0; i < 8; i++) {
                zacc[i] += ar[i];
#pragma unroll
                for (int j = 0; j < 8; j++)
                    acc[i][j] = fmaf(ar[i], br[j], acc[i][j]);
            }
        }
        __syncthreads();
    }

    // row sums Z (each row's zacc is replicated across the 16 tx threads; take tx==0)
    if (tx == 0) {
#pragma unroll
        for (int i = 0; i < 8; i++) sZ[ty * 8 + i] = zacc[i];
    }
    __syncthreads();

#pragma unroll
    for (int i = 0; i < 8; i++) {
        int gi = i0 + ty * 8 + i;
        float zr = 1.0f / sZ[ty * 8 + i];
        float* yr = g_y + ((size_t)b * NN + gi) * DD + d0 + tx * 8;
#pragma unroll
        for (int j = 0; j < 8; j++) yr[j] = acc[i][j] * zr;
    }
}

// ---------------- launch ----------------
extern "C" void kernel_launch(void* const* d_in, const int* in_sizes, int n_in,
                              void* d_out, int out_size)
{
    const float* inputs = (const float*)d_in[0];
    const float* adj    = (const float*)d_in[1];
    const float* W_fc   = (const float*)d_in[2];
    const float* b_fc   = (const float*)d_in[3];
    const float* w_q    = (const float*)d_in[4];
    const float* b_q    = (const float*)d_in[5];
    const float* w_k    = (const float*)d_in[6];
    const float* b_k    = (const float*)d_in[7];
    const float* W_uy   = (const float*)d_in[8];
    const float* b_uy   = (const float*)d_in[9];
    const float* W_ux   = (const float*)d_in[10];
    const float* b_ux   = (const float*)d_in[11];
    const float* W_ry   = (const float*)d_in[12];
    const float* b_ry   = (const float*)d_in[13];
    const float* W_rx   = (const float*)d_in[14];
    const float* b_rx   = (const float*)d_in[15];
    const float* W_ty   = (const float*)d_in[16];
    const float* b_ty   = (const float*)d_in[17];
    const float* W_tx   = (const float*)d_in[18];
    const float* b_tx   = (const float*)d_in[19];
    float* out = (float*)d_out;

    float *fp, *y, *u, *rx;
    cudaGetSymbolAddress((void**)&fp, g_fp);
    cudaGetSymbolAddress((void**)&y,  g_y);
    cudaGetSymbolAddress((void**)&u,  g_u);
    cudaGetSymbolAddress((void**)&rx, g_rx);

    dim3 gG(DD / 128, MM / 128);   // (6, 128)
    dim3 gA(DD / 128, NN / 128, NB); // (6, 8, 16)

    // 1) feat_proj = inputs @ W_fc^T + b_fc
    gemm_dual<<<gG, 256>>>(inputs, W_fc, nullptr, nullptr, b_fc, nullptr,
                           nullptr, nullptr, fp, DD, 0);
    // 2) q, k
    qk_kernel<<<MM, 256>>>(w_q, b_q, w_k, b_k);
    // 3) fused masked attention -> y
    attn_kernel<<<gA, 256>>>(adj);
    // 4) u = sigmoid(y@W_uy^T + inputs@W_ux^T + b_uy + b_ux)
    gemm_dual<<<gG, 256>>>(y, W_uy, inputs, W_ux, b_uy, b_ux,
                           nullptr, nullptr, u, 2 * DD, 1);
    // 5) rx = sigmoid(y@W_ry^T + inputs@W_rx^T + b_ry + b_rx) * inputs
    gemm_dual<<<gG, 256>>>(y, W_ry, inputs, W_rx, b_ry, b_rx,
                           inputs, nullptr, rx, 2 * DD, 2);
    // 6) out = (1-u)*inputs + u*tanh(y@W_ty^T + rx@W_tx^T + b_ty + b_tx)
    gemm_dual<<<gG, 256>>>(y, W_ty, rx, W_tx, b_ty, b_tx,
                           inputs, u, out, 2 * DD, 3);
}

// round 3
// speedup vs baseline: 1.9268x; 1.9268x over previous
#include <cuda_runtime.h>
#include <cuda_bf16.h>
#include <cstdint>
#include <math.h>

#define NB 16
#define NN 1024
#define DD 768
#define MM (NB * NN)

typedef __nv_bfloat16 bf;

// ---------------- scratch ----------------
__device__ bf    g_in_hi[(size_t)MM * DD], g_in_lo[(size_t)MM * DD];
__device__ float g_fp[(size_t)MM * DD];
__device__ bf    g_fpT_hi[(size_t)NB * DD * NN], g_fpT_lo[(size_t)NB * DD * NN];
__device__ bf    g_y_hi[(size_t)MM * DD], g_y_lo[(size_t)MM * DD];
__device__ bf    g_rx_hi[(size_t)MM * DD], g_rx_lo[(size_t)MM * DD];
__device__ float g_u[(size_t)MM * DD];
__device__ bf    g_E_hi[(size_t)NB * NN * NN], g_E_lo[(size_t)NB * NN * NN];
__device__ float g_Z[MM];
__device__ float g_q[MM], g_k[MM];
__device__ bf    g_W_hi[(size_t)7 * DD * DD], g_W_lo[(size_t)7 * DD * DD];

// ---------------- fp32 -> (hi,lo) bf16 split ----------------
__global__ __launch_bounds__(256) void split_kernel(
    const float* __restrict__ src, bf* __restrict__ hi, bf* __restrict__ lo, int n4)
{
    int i = blockIdx.x * 256 + threadIdx.x;
    if (i >= n4) return;
    float4 v = ((const float4*)src)[i];
    float x[4] = {v.x, v.y, v.z, v.w};
    __nv_bfloat162 ph[2], pl[2];
#pragma unroll
    for (int p = 0; p < 2; p++) {
        bf h0 = __float2bfloat16(x[p * 2]);
        bf h1 = __float2bfloat16(x[p * 2 + 1]);
        bf l0 = __float2bfloat16(x[p * 2] - __bfloat162float(h0));
        bf l1 = __float2bfloat16(x[p * 2 + 1] - __bfloat162float(h1));
        ph[p] = __halves2bfloat162(h0, h1);
        pl[p] = __halves2bfloat162(l0, l1);
    }
    ((__nv_bfloat162*)hi)[i * 2]     = ph[0];
    ((__nv_bfloat162*)hi)[i * 2 + 1] = ph[1];
    ((__nv_bfloat162*)lo)[i * 2]     = pl[0];
    ((__nv_bfloat162*)lo)[i * 2 + 1] = pl[1];
}

// ---------------- q/k per-row dots (reads fp32 feat_proj) ----------------
__global__ __launch_bounds__(256) void qk_kernel(
    const float* __restrict__ wq, const float* __restrict__ bq,
    const float* __restrict__ wk, const float* __restrict__ bk)
{
    const int m = blockIdx.x;
    const float* row = g_fp + (size_t)m * DD;
    const int tid = threadIdx.x;
    float sq = 0.0f, sk = 0.0f;
    for (int d = tid; d < DD; d += 256) {
        float v = row[d];
        sq = fmaf(v, wq[d], sq);
        sk = fmaf(v, wk[d], sk);
    }
#pragma unroll
    for (int o = 16; o; o >>= 1) {
        sq += __shfl_down_sync(0xFFFFFFFFu, sq, o);
        sk += __shfl_down_sync(0xFFFFFFFFu, sk, o);
    }
    __shared__ float rq[8], rk[8];
    if ((tid & 31) == 0) { rq[tid >> 5] = sq; rk[tid >> 5] = sk; }
    __syncthreads();
    if (tid == 0) {
        float a = 0.0f, c = 0.0f;
#pragma unroll
        for (int w = 0; w < 8; w++) { a += rq[w]; c += rk[w]; }
        g_q[m] = a + bq[0];
        g_k[m] = c + bk[0];
    }
}

// ---------------- E = adj * exp(lrelu(q+k)), hi/lo + row sums ----------------
__global__ __launch_bounds__(256) void maskexp_kernel(const float* __restrict__ adj)
{
    const int row = blockIdx.x;            // global row: b*NN + i
    const int b = row >> 10;
    const float qi = g_q[row];
    const float* arow = adj + (size_t)row * NN;
    const float* kb = g_k + b * NN;
    bf* ehi = g_E_hi + (size_t)row * NN;
    bf* elo = g_E_lo + (size_t)row * NN;

    float s = 0.0f;
    for (int j = threadIdx.x; j < NN; j += 256) {
        float a = arow[j];
        float v = qi + kb[j];
        float lr = v >= 0.0f ? v : 0.01f * v;
        float e = (a > 0.5f) ? expf(lr) : 0.0f;
        s += e;
        bf h = __float2bfloat16(e);
        ehi[j] = h;
        elo[j] = __float2bfloat16(e - __bfloat162float(h));
    }
#pragma unroll
    for (int o = 16; o; o >>= 1) s += __shfl_down_sync(0xFFFFFFFFu, s, o);
    __shared__ float red[8];
    if ((threadIdx.x & 31) == 0) red[threadIdx.x >> 5] = s;
    __syncthreads();
    if (threadIdx.x == 0) {
        float t = 0.0f;
#pragma unroll
        for (int w = 0; w < 8; w++) t += red[w];
        g_Z[row] = t;
    }
}

// ---------------- bf16x3 split-precision MMA GEMM ----------------
// C[m,n] = sum_k A[m,k] * B[n,k]  (A,B given as hi/lo bf16 pairs)
// BM=BN=128, BK=64, 256 threads (8 warps: 4x2), warp tile 32x64.
// modes: 0 = v+b1 -> outF fp32 [m][n]  AND transposed hi/lo outH/outL [b][n][j]
//        1 = sigmoid(v+b1+b2)          -> outF
//        2 = sigmoid(v+b1+b2)*X        -> outH/outL (hi/lo, row-major)
//        3 = (1-U)*X + U*tanh(v+b1+b2) -> outF
//        4 = v / Z[m]                  -> outH/outL (hi/lo, row-major)
#define TILE_B 16384

__device__ __forceinline__ uint32_t sw_off(int r, int c) {
    return (uint32_t)(r * 128 + ((c ^ (r & 7)) << 4));
}

__device__ __forceinline__ void ldsm4(uint32_t addr, uint32_t& r0, uint32_t& r1,
                                      uint32_t& r2, uint32_t& r3) {
    asm volatile("ldmatrix.sync.aligned.m8n8.x4.shared.b16 {%0,%1,%2,%3}, [%4];"
                 : "=r"(r0), "=r"(r1), "=r"(r2), "=r"(r3) : "r"(addr));
}

__device__ __forceinline__ void mma_bf16(float* c, const uint32_t* a, const uint32_t* b) {
    asm volatile(
        "mma.sync.aligned.m16n8k16.row.col.f32.bf16.bf16.f32 "
        "{%0,%1,%2,%3}, {%4,%5,%6,%7}, {%8,%9}, {%0,%1,%2,%3};"
        : "+f"(c[0]), "+f"(c[1]), "+f"(c[2]), "+f"(c[3])
        : "r"(a[0]), "r"(a[1]), "r"(a[2]), "r"(a[3]), "r"(b[0]), "r"(b[1]));
}

__global__ __launch_bounds__(256) void mma_gemm(
    const bf* __restrict__ A1h, const bf* __restrict__ A1l,
    const bf* __restrict__ B1h, const bf* __restrict__ B1l,
    const bf* __restrict__ A2h, const bf* __restrict__ A2l,
    const bf* __restrict__ B2h, const bf* __restrict__ B2l,
    const float* __restrict__ b1, const float* __restrict__ b2,
    const float* __restrict__ X, const float* __restrict__ U,
    const float* __restrict__ Zv,
    float* __restrict__ outF, bf* __restrict__ outH, bf* __restrict__ outL,
    int K, int K1, int lda, int ldb, size_t bstrideB, int mode)
{
    extern __shared__ char smem[];
    char* As_hi = smem;
    char* As_lo = smem + TILE_B;
    char* Bs_hi = smem + 2 * TILE_B;
    char* Bs_lo = smem + 3 * TILE_B;

    const int tid = threadIdx.x;
    const int lane = tid & 31;
    const int warp = tid >> 5;
    const int wy = warp >> 1;          // 0..3
    const int wx = warp & 1;           // 0..1
    const int m0 = blockIdx.y * 128;
    const int n0 = blockIdx.x * 128;

    const size_t bOffB = (size_t)(m0 >> 10) * bstrideB;

    // loader mapping: each thread: row = tid/2, chunks (tid&1)*4 .. +3
    const int lr = tid >> 1;
    const int lc4 = (tid & 1) * 4;

    float acc[2][8][4];
#pragma unroll
    for (int mt = 0; mt < 2; mt++)
#pragma unroll
        for (int nt = 0; nt < 8; nt++)
#pragma unroll
            for (int v = 0; v < 4; v++) acc[mt][nt][v] = 0.0f;

    for (int kb = 0; kb < K; kb += 64) {
        const bf *Ah, *Al, *Bh, *Bl;
        int ko;
        if (kb < K1) { Ah = A1h; Al = A1l; Bh = B1h; Bl = B1l; ko = kb; }
        else         { Ah = A2h; Al = A2l; Bh = B2h; Bl = B2l; ko = kb - K1; }

        // global -> smem (swizzled)
        {
            size_t abase = (size_t)(m0 + lr) * lda + ko;
            size_t bbase = bOffB + (size_t)(n0 + lr) * ldb + ko;
#pragma unroll
            for (int c = 0; c < 4; c++) {
                int ch = lc4 + c;
                uint32_t so = sw_off(lr, ch);
                *(uint4*)(As_hi + so) = *(const uint4*)(Ah + abase + ch * 8);
                *(uint4*)(As_lo + so) = *(const uint4*)(Al + abase + ch * 8);
                *(uint4*)(Bs_hi + so) = *(const uint4*)(Bh + bbase + ch * 8);
                *(uint4*)(Bs_lo + so) = *(const uint4*)(Bl + bbase + ch * 8);
            }
        }
        __syncthreads();

#pragma unroll
        for (int ks = 0; ks < 4; ks++) {
            uint32_t ah[2][4], al[2][4], bh[8][2], blo[8][2];
            // A fragments
#pragma unroll
            for (int mt = 0; mt < 2; mt++) {
                int r = wy * 32 + mt * 16 + (lane & 15);
                int ch = ks * 2 + (lane >> 4);
                uint32_t so = sw_off(r, ch);
                ldsm4((uint32_t)__cvta_generic_to_shared(As_hi + so),
                      ah[mt][0], ah[mt][1], ah[mt][2], ah[mt][3]);
                ldsm4((uint32_t)__cvta_generic_to_shared(As_lo + so),
                      al[mt][0], al[mt][1], al[mt][2], al[mt][3]);
            }
            // B fragments (pairs of n-tiles per ldmatrix.x4)
#pragma unroll
            for (int np = 0; np < 4; np++) {
                int r = wx * 64 + np * 16 + (lane & 7) + ((lane >> 4) << 3);
                int ch = ks * 2 + ((lane >> 3) & 1);
                uint32_t so = sw_off(r, ch);
                ldsm4((uint32_t)__cvta_generic_to_shared(Bs_hi + so),
                      bh[np * 2][0], bh[np * 2][1], bh[np * 2 + 1][0], bh[np * 2 + 1][1]);
                ldsm4((uint32_t)__cvta_generic_to_shared(Bs_lo + so),
                      blo[np * 2][0], blo[np * 2][1], blo[np * 2 + 1][0], blo[np * 2 + 1][1]);
            }
            // 3 passes: hi*hi, hi*lo, lo*hi
#pragma unroll
            for (int mt = 0; mt < 2; mt++)
#pragma unroll
                for (int nt = 0; nt < 8; nt++)
                    mma_bf16(acc[mt][nt], ah[mt], bh[nt]);
#pragma unroll
            for (int mt = 0; mt < 2; mt++)
#pragma unroll
                for (int nt = 0; nt < 8; nt++)
                    mma_bf16(acc[mt][nt], ah[mt], blo[nt]);
#pragma unroll
            for (int mt = 0; mt < 2; mt++)
#pragma unroll
                for (int nt = 0; nt < 8; nt++)
                    mma_bf16(acc[mt][nt], al[mt], bh[nt]);
        }
        __syncthreads();
    }

    // ---------------- epilogue ----------------
    const int mbase = m0 + wy * 32;
    const int nbase = n0 + wx * 64;
#pragma unroll
    for (int mt = 0; mt < 2; mt++) {
#pragma unroll
        for (int nt = 0; nt < 8; nt++) {
            int c0 = nbase + nt * 8 + (lane & 3) * 2;
            int r0 = mbase + mt * 16 + (lane >> 2);
            float* ac = acc[mt][nt];
#pragma unroll
            for (int h = 0; h < 2; h++) {
                int r = r0 + h * 8;
                float v0 = ac[h * 2], v1 = ac[h * 2 + 1];
                size_t off = (size_t)r * DD + c0;
                if (mode == 0) {
                    v0 += b1[c0]; v1 += b1[c0 + 1];
                    *(float2*)(outF + off) = make_float2(v0, v1);
                    int bb = r >> 10, jj = r & 1023;
                    size_t tbase = (size_t)bb * DD * NN + (size_t)c0 * NN + jj;
                    bf h0 = __float2bfloat16(v0);
                    bf h1 = __float2bfloat16(v1);
                    outH[tbase]      = h0;
                    outL[tbase]      = __float2bfloat16(v0 - __bfloat162float(h0));
                    outH[tbase + NN] = h1;
                    outL[tbase + NN] = __float2bfloat16(v1 - __bfloat162float(h1));
                } else if (mode == 4) {
                    float zr = 1.0f / Zv[r];
                    v0 *= zr; v1 *= zr;
                    bf h0 = __float2bfloat16(v0);
                    bf h1 = __float2bfloat16(v1);
                    *(__nv_bfloat162*)(outH + off) = __halves2bfloat162(h0, h1);
                    *(__nv_bfloat162*)(outL + off) = __halves2bfloat162(
                        __float2bfloat16(v0 - __bfloat162float(h0)),
                        __float2bfloat16(v1 - __bfloat162float(h1)));
                } else if (mode == 1) {
                    v0 += b1[c0] + b2[c0];
                    v1 += b1[c0 + 1] + b2[c0 + 1];
                    float s0 = 1.0f / (1.0f + expf(-v0));
                    float s1 = 1.0f / (1.0f + expf(-v1));
                    *(float2*)(outF + off) = make_float2(s0, s1);
                } else if (mode == 2) {
                    v0 += b1[c0] + b2[c0];
                    v1 += b1[c0 + 1] + b2[c0 + 1];
                    float s0 = (1.0f / (1.0f + expf(-v0))) * X[off];
                    float s1 = (1.0f / (1.0f + expf(-v1))) * X[off + 1];
                    bf h0 = __float2bfloat16(s0);
                    bf h1 = __float2bfloat16(s1);
                    *(__nv_bfloat162*)(outH + off) = __halves2bfloat162(h0, h1);
                    *(__nv_bfloat162*)(outL + off) = __halves2bfloat162(
                        __float2bfloat16(s0 - __bfloat162float(h0)),
                        __float2bfloat16(s1 - __bfloat162float(h1)));
                } else {
                    v0 += b1[c0] + b2[c0];
                    v1 += b1[c0 + 1] + b2[c0 + 1];
                    float t0 = tanhf(v0), t1 = tanhf(v1);
                    float u0 = U[off], u1 = U[off + 1];
                    float x0 = X[off], x1 = X[off + 1];
                    *(float2*)(outF + off) =
                        make_float2(x0 + u0 * (t0 - x0), x1 + u1 * (t1 - x1));
                }
            }
        }
    }
}

// ---------------- launch ----------------
extern "C" void kernel_launch(void* const* d_in, const int* in_sizes, int n_in,
                              void* d_out, int out_size)
{
    const float* inputs = (const float*)d_in[0];
    const float* adj    = (const float*)d_in[1];
    const float* W_fc   = (const float*)d_in[2];
    const float* b_fc   = (const float*)d_in[3];
    const float* w_q    = (const float*)d_in[4];
    const float* b_q    = (const float*)d_in[5];
    const float* w_k    = (const float*)d_in[6];
    const float* b_k    = (const float*)d_in[7];
    const float* W_uy   = (const float*)d_in[8];
    const float* b_uy   = (const float*)d_in[9];
    const float* W_ux   = (const float*)d_in[10];
    const float* b_ux   = (const float*)d_in[11];
    const float* W_ry   = (const float*)d_in[12];
    const float* b_ry   = (const float*)d_in[13];
    const float* W_rx   = (const float*)d_in[14];
    const float* b_rx   = (const float*)d_in[15];
    const float* W_ty   = (const float*)d_in[16];
    const float* b_ty   = (const float*)d_in[17];
    const float* W_tx   = (const float*)d_in[18];
    const float* b_tx   = (const float*)d_in[19];
    float* out = (float*)d_out;

    bf *in_hi, *in_lo, *fpT_hi, *fpT_lo, *y_hi, *y_lo, *rx_hi, *rx_lo;
    bf *E_hi, *E_lo, *W_hi, *W_lo;
    float *fp, *u, *Z;
    cudaGetSymbolAddress((void**)&in_hi, g_in_hi);
    cudaGetSymbolAddress((void**)&in_lo, g_in_lo);
    cudaGetSymbolAddress((void**)&fp, g_fp);
    cudaGetSymbolAddress((void**)&fpT_hi, g_fpT_hi);
    cudaGetSymbolAddress((void**)&fpT_lo, g_fpT_lo);
    cudaGetSymbolAddress((void**)&y_hi, g_y_hi);
    cudaGetSymbolAddress((void**)&y_lo, g_y_lo);
    cudaGetSymbolAddress((void**)&rx_hi, g_rx_hi);
    cudaGetSymbolAddress((void**)&rx_lo, g_rx_lo);
    cudaGetSymbolAddress((void**)&u, g_u);
    cudaGetSymbolAddress((void**)&E_hi, g_E_hi);
    cudaGetSymbolAddress((void**)&E_lo, g_E_lo);
    cudaGetSymbolAddress((void**)&Z, g_Z);
    cudaGetSymbolAddress((void**)&W_hi, g_W_hi);
    cudaGetSymbolAddress((void**)&W_lo, g_W_lo);

    cudaFuncSetAttribute(mma_gemm, cudaFuncAttributeMaxDynamicSharedMemorySize, 4 * TILE_B);

    // split inputs + weights
    const int WSZ = DD * DD;
    split_kernel<<<(MM * DD / 4 + 255) / 256, 256>>>(inputs, in_hi, in_lo, MM * DD / 4);
    const float* Ws[7] = {W_fc, W_uy, W_ux, W_ry, W_rx, W_ty, W_tx};
    for (int i = 0; i < 7; i++)
        split_kernel<<<(WSZ / 4 + 255) / 256, 256>>>(Ws[i], W_hi + (size_t)i * WSZ,
                                                     W_lo + (size_t)i * WSZ, WSZ / 4);
    bf* Wfc_h = W_hi;                 bf* Wfc_l = W_lo;
    bf* Wuy_h = W_hi + (size_t)1*WSZ; bf* Wuy_l = W_lo + (size_t)1*WSZ;
    bf* Wux_h = W_hi + (size_t)2*WSZ; bf* Wux_l = W_lo + (size_t)2*WSZ;
    bf* Wry_h = W_hi + (size_t)3*WSZ; bf* Wry_l = W_lo + (size_t)3*WSZ;
    bf* Wrx_h = W_hi + (size_t)4*WSZ; bf* Wrx_l = W_lo + (size_t)4*WSZ;
    bf* Wty_h = W_hi + (size_t)5*WSZ; bf* Wty_l = W_lo + (size_t)5*WSZ;
    bf* Wtx_h = W_hi + (size_t)6*WSZ; bf* Wtx_l = W_lo + (size_t)6*WSZ;

    dim3 grid(DD / 128, MM / 128);  // (6, 128)
    size_t smem = 4 * TILE_B;

    // 1) feat_proj (fp32 + transposed hi/lo)
    mma_gemm<<<grid, 256, smem>>>(in_hi, in_lo, Wfc_h, Wfc_l,
                                  in_hi, in_lo, Wfc_h, Wfc_l,
                                  b_fc, nullptr, nullptr, nullptr, nullptr,
                                  fp, fpT_hi, fpT_lo,
                                  DD, DD, DD, DD, 0, 0);
    // 2) q, k
    qk_kernel<<<MM, 256>>>(w_q, b_q, w_k, b_k);
    // 3) E, Z
    maskexp_kernel<<<MM, 256>>>(adj);
    // 4) y = (E @ fpT) / Z  (batched B)
    mma_gemm<<<grid, 256, smem>>>(E_hi, E_lo, fpT_hi, fpT_lo,
                                  E_hi, E_lo, fpT_hi, fpT_lo,
                                  nullptr, nullptr, nullptr, nullptr, Z,
                                  nullptr, y_hi, y_lo,
                                  NN, NN, NN, NN, (size_t)DD * NN, 4);
    // 5) u
    mma_gemm<<<grid, 256, smem>>>(y_hi, y_lo, Wuy_h, Wuy_l,
                                  in_hi, in_lo, Wux_h, Wux_l,
                                  b_uy, b_ux, nullptr, nullptr, nullptr,
                                  u, nullptr, nullptr,
                                  2 * DD, DD, DD, DD, 0, 1);
    // 6) rx = sigmoid(...) * inputs
    mma_gemm<<<grid, 256, smem>>>(y_hi, y_lo, Wry_h, Wry_l,
                                  in_hi, in_lo, Wrx_h, Wrx_l,
                                  b_ry, b_rx, inputs, nullptr, nullptr,
                                  nullptr, rx_hi, rx_lo,
                                  2 * DD, DD, DD, DD, 0, 2);
    // 7) out
    mma_gemm<<<grid, 256, smem>>>(y_hi, y_lo, Wty_h, Wty_l,
                                  rx_hi, rx_lo, Wtx_h, Wtx_l,
                                  b_ty, b_tx, inputs, u, nullptr,
                                  out, nullptr, nullptr,
                                  2 * DD, DD, DD, DD, 0, 3);
}

// round 4
// speedup vs baseline: 2.4121x; 1.2518x over previous
#include <cuda_runtime.h>
#include <cuda_bf16.h>
#include <cstdint>
#include <math.h>

#define NB 16
#define NN 1024
#define DD 768
#define MM (NB * NN)

typedef __nv_bfloat16 bf;

// ---------------- scratch ----------------
__device__ bf    g_in_hi[(size_t)MM * DD], g_in_lo[(size_t)MM * DD];
__device__ float g_fp[(size_t)MM * DD];
__device__ bf    g_fpT_hi[(size_t)NB * DD * NN], g_fpT_lo[(size_t)NB * DD * NN];
__device__ bf    g_y_hi[(size_t)MM * DD], g_y_lo[(size_t)MM * DD];
__device__ bf    g_rx_hi[(size_t)MM * DD], g_rx_lo[(size_t)MM * DD];
__device__ float g_u[(size_t)MM * DD];
__device__ bf    g_E_hi[(size_t)NB * NN * NN], g_E_lo[(size_t)NB * NN * NN];
__device__ float g_Z[MM];
__device__ float g_q[MM], g_k[MM];
__device__ bf    g_W_hi[(size_t)7 * DD * DD], g_W_lo[(size_t)7 * DD * DD];

// ---------------- fp32 -> (hi,lo) bf16 split ----------------
__global__ __launch_bounds__(256) void split_kernel(
    const float* __restrict__ src, bf* __restrict__ hi, bf* __restrict__ lo, int n4)
{
    int i = blockIdx.x * 256 + threadIdx.x;
    if (i >= n4) return;
    float4 v = ((const float4*)src)[i];
    float x[4] = {v.x, v.y, v.z, v.w};
    __nv_bfloat162 ph[2], pl[2];
#pragma unroll
    for (int p = 0; p < 2; p++) {
        bf h0 = __float2bfloat16(x[p * 2]);
        bf h1 = __float2bfloat16(x[p * 2 + 1]);
        bf l0 = __float2bfloat16(x[p * 2] - __bfloat162float(h0));
        bf l1 = __float2bfloat16(x[p * 2 + 1] - __bfloat162float(h1));
        ph[p] = __halves2bfloat162(h0, h1);
        pl[p] = __halves2bfloat162(l0, l1);
    }
    ((__nv_bfloat162*)hi)[i * 2]     = ph[0];
    ((__nv_bfloat162*)hi)[i * 2 + 1] = ph[1];
    ((__nv_bfloat162*)lo)[i * 2]     = pl[0];
    ((__nv_bfloat162*)lo)[i * 2 + 1] = pl[1];
}

// ---------------- q/k per-row dots (reads fp32 feat_proj) ----------------
__global__ __launch_bounds__(256) void qk_kernel(
    const float* __restrict__ wq, const float* __restrict__ bq,
    const float* __restrict__ wk, const float* __restrict__ bk)
{
    const int m = blockIdx.x;
    const float* row = g_fp + (size_t)m * DD;
    const int tid = threadIdx.x;
    float sq = 0.0f, sk = 0.0f;
    for (int d = tid; d < DD; d += 256) {
        float v = row[d];
        sq = fmaf(v, wq[d], sq);
        sk = fmaf(v, wk[d], sk);
    }
#pragma unroll
    for (int o = 16; o; o >>= 1) {
        sq += __shfl_down_sync(0xFFFFFFFFu, sq, o);
        sk += __shfl_down_sync(0xFFFFFFFFu, sk, o);
    }
    __shared__ float rq[8], rk[8];
    if ((tid & 31) == 0) { rq[tid >> 5] = sq; rk[tid >> 5] = sk; }
    __syncthreads();
    if (tid == 0) {
        float a = 0.0f, c = 0.0f;
#pragma unroll
        for (int w = 0; w < 8; w++) { a += rq[w]; c += rk[w]; }
        g_q[m] = a + bq[0];
        g_k[m] = c + bk[0];
    }
}

// ---------------- E = adj * exp(lrelu(q+k)), hi/lo + row sums ----------------
__global__ __launch_bounds__(256) void maskexp_kernel(const float* __restrict__ adj)
{
    const int row = blockIdx.x;
    const int b = row >> 10;
    const float qi = g_q[row];
    const float* arow = adj + (size_t)row * NN;
    const float* kb = g_k + b * NN;
    bf* ehi = g_E_hi + (size_t)row * NN;
    bf* elo = g_E_lo + (size_t)row * NN;

    float s = 0.0f;
    for (int j = threadIdx.x; j < NN; j += 256) {
        float a = arow[j];
        float v = qi + kb[j];
        float lr = v >= 0.0f ? v : 0.01f * v;
        float e = (a > 0.5f) ? expf(lr) : 0.0f;
        s += e;
        bf h = __float2bfloat16(e);
        ehi[j] = h;
        elo[j] = __float2bfloat16(e - __bfloat162float(h));
    }
#pragma unroll
    for (int o = 16; o; o >>= 1) s += __shfl_down_sync(0xFFFFFFFFu, s, o);
    __shared__ float red[8];
    if ((threadIdx.x & 31) == 0) red[threadIdx.x >> 5] = s;
    __syncthreads();
    if (threadIdx.x == 0) {
        float t = 0.0f;
#pragma unroll
        for (int w = 0; w < 8; w++) t += red[w];
        g_Z[row] = t;
    }
}

// ---------------- bf16x3 split-precision MMA GEMM (cp.async 2-stage pipeline) ----------------
#define TILE_B 16384
#define STAGE_B (4 * TILE_B)          // 64KB per stage (As_hi, As_lo, Bs_hi, Bs_lo)

__device__ __forceinline__ uint32_t sw_off(int r, int c) {
    return (uint32_t)(r * 128 + ((c ^ (r & 7)) << 4));
}

__device__ __forceinline__ void ldsm4(uint32_t addr, uint32_t& r0, uint32_t& r1,
                                      uint32_t& r2, uint32_t& r3) {
    asm volatile("ldmatrix.sync.aligned.m8n8.x4.shared.b16 {%0,%1,%2,%3}, [%4];"
                 : "=r"(r0), "=r"(r1), "=r"(r2), "=r"(r3) : "r"(addr));
}

__device__ __forceinline__ void mma_bf16(float* c, const uint32_t* a, const uint32_t* b) {
    asm volatile(
        "mma.sync.aligned.m16n8k16.row.col.f32.bf16.bf16.f32 "
        "{%0,%1,%2,%3}, {%4,%5,%6,%7}, {%8,%9}, {%0,%1,%2,%3};"
        : "+f"(c[0]), "+f"(c[1]), "+f"(c[2]), "+f"(c[3])
        : "r"(a[0]), "r"(a[1]), "r"(a[2]), "r"(a[3]), "r"(b[0]), "r"(b[1]));
}

__device__ __forceinline__ void cp16(char* smem_dst, const void* gsrc) {
    uint32_t s = (uint32_t)__cvta_generic_to_shared(smem_dst);
    asm volatile("cp.async.cg.shared.global [%0], [%1], 16;" :: "r"(s), "l"(gsrc));
}

__global__ __launch_bounds__(256) void mma_gemm(
    const bf* __restrict__ A1h, const bf* __restrict__ A1l,
    const bf* __restrict__ B1h, const bf* __restrict__ B1l,
    const bf* __restrict__ A2h, const bf* __restrict__ A2l,
    const bf* __restrict__ B2h, const bf* __restrict__ B2l,
    const float* __restrict__ b1, const float* __restrict__ b2,
    const float* __restrict__ X, const float* __restrict__ U,
    const float* __restrict__ Zv,
    float* __restrict__ outF, bf* __restrict__ outH, bf* __restrict__ outL,
    int K, int K1, int lda, int ldb, size_t bstrideB, int mode)
{
    extern __shared__ char smem[];

    const int tid = threadIdx.x;
    const int lane = tid & 31;
    const int warp = tid >> 5;
    const int wy = warp >> 1;          // 0..3
    const int wx = warp & 1;           // 0..1
    const int m0 = blockIdx.y * 128;
    const int n0 = blockIdx.x * 128;

    const size_t bOffB = (size_t)(m0 >> 10) * bstrideB;

    const int lr = tid >> 1;
    const int lc4 = (tid & 1) * 4;

    float acc[2][8][4];
#pragma unroll
    for (int mt = 0; mt < 2; mt++)
#pragma unroll
        for (int nt = 0; nt < 8; nt++)
#pragma unroll
            for (int v = 0; v < 4; v++) acc[mt][nt][v] = 0.0f;

    const int NT = K / 64;

    // issue async loads of ktile kt into stage st
    auto load_tile = [&](int kt, int st) {
        int kb = kt * 64;
        const bf *Ah, *Al, *Bh, *Bl;
        int ko;
        if (kb < K1) { Ah = A1h; Al = A1l; Bh = B1h; Bl = B1l; ko = kb; }
        else         { Ah = A2h; Al = A2l; Bh = B2h; Bl = B2l; ko = kb - K1; }
        char* As_hi = smem + st * STAGE_B;
        char* As_lo = As_hi + TILE_B;
        char* Bs_hi = As_hi + 2 * TILE_B;
        char* Bs_lo = As_hi + 3 * TILE_B;
        size_t abase = (size_t)(m0 + lr) * lda + ko;
        size_t bbase = bOffB + (size_t)(n0 + lr) * ldb + ko;
#pragma unroll
        for (int c = 0; c < 4; c++) {
            int ch = lc4 + c;
            uint32_t so = sw_off(lr, ch);
            cp16(As_hi + so, Ah + abase + ch * 8);
            cp16(As_lo + so, Al + abase + ch * 8);
            cp16(Bs_hi + so, Bh + bbase + ch * 8);
            cp16(Bs_lo + so, Bl + bbase + ch * 8);
        }
    };

    // prologue: stage 0
    load_tile(0, 0);
    asm volatile("cp.async.commit_group;");

    for (int kt = 0; kt < NT; kt++) {
        if (kt + 1 < NT) load_tile(kt + 1, (kt + 1) & 1);
        asm volatile("cp.async.commit_group;");
        asm volatile("cp.async.wait_group 1;");
        __syncthreads();

        char* As_hi = smem + (kt & 1) * STAGE_B;
        char* As_lo = As_hi + TILE_B;
        char* Bs_hi = As_hi + 2 * TILE_B;
        char* Bs_lo = As_hi + 3 * TILE_B;

#pragma unroll
        for (int ks = 0; ks < 4; ks++) {
            uint32_t ah[2][4], al[2][4], bh[8][2], blo[8][2];
#pragma unroll
            for (int mt = 0; mt < 2; mt++) {
                int r = wy * 32 + mt * 16 + (lane & 15);
                int ch = ks * 2 + (lane >> 4);
                uint32_t so = sw_off(r, ch);
                ldsm4((uint32_t)__cvta_generic_to_shared(As_hi + so),
                      ah[mt][0], ah[mt][1], ah[mt][2], ah[mt][3]);
                ldsm4((uint32_t)__cvta_generic_to_shared(As_lo + so),
                      al[mt][0], al[mt][1], al[mt][2], al[mt][3]);
            }
#pragma unroll
            for (int np = 0; np < 4; np++) {
                int r = wx * 64 + np * 16 + (lane & 7) + ((lane >> 4) << 3);
                int ch = ks * 2 + ((lane >> 3) & 1);
                uint32_t so = sw_off(r, ch);
                ldsm4((uint32_t)__cvta_generic_to_shared(Bs_hi + so),
                      bh[np * 2][0], bh[np * 2][1], bh[np * 2 + 1][0], bh[np * 2 + 1][1]);
                ldsm4((uint32_t)__cvta_generic_to_shared(Bs_lo + so),
                      blo[np * 2][0], blo[np * 2][1], blo[np * 2 + 1][0], blo[np * 2 + 1][1]);
            }
#pragma unroll
            for (int mt = 0; mt < 2; mt++)
#pragma unroll
                for (int nt = 0; nt < 8; nt++)
                    mma_bf16(acc[mt][nt], ah[mt], bh[nt]);
#pragma unroll
            for (int mt = 0; mt < 2; mt++)
#pragma unroll
                for (int nt = 0; nt < 8; nt++)
                    mma_bf16(acc[mt][nt], ah[mt], blo[nt]);
#pragma unroll
            for (int mt = 0; mt < 2; mt++)
#pragma unroll
                for (int nt = 0; nt < 8; nt++)
                    mma_bf16(acc[mt][nt], al[mt], bh[nt]);
        }
        __syncthreads();
    }

    // ---------------- epilogue ----------------
    const int mbase = m0 + wy * 32;
    const int nbase = n0 + wx * 64;
#pragma unroll
    for (int mt = 0; mt < 2; mt++) {
#pragma unroll
        for (int nt = 0; nt < 8; nt++) {
            int c0 = nbase + nt * 8 + (lane & 3) * 2;
            int r0 = mbase + mt * 16 + (lane >> 2);
            float* ac = acc[mt][nt];
#pragma unroll
            for (int h = 0; h < 2; h++) {
                int r = r0 + h * 8;
                float v0 = ac[h * 2], v1 = ac[h * 2 + 1];
                size_t off = (size_t)r * DD + c0;
                if (mode == 0) {
                    v0 += b1[c0]; v1 += b1[c0 + 1];
                    *(float2*)(outF + off) = make_float2(v0, v1);
                    int bb = r >> 10, jj = r & 1023;
                    size_t tbase = (size_t)bb * DD * NN + (size_t)c0 * NN + jj;
                    bf h0 = __float2bfloat16(v0);
                    bf h1 = __float2bfloat16(v1);
                    outH[tbase]      = h0;
                    outL[tbase]      = __float2bfloat16(v0 - __bfloat162float(h0));
                    outH[tbase + NN] = h1;
                    outL[tbase + NN] = __float2bfloat16(v1 - __bfloat162float(h1));
                } else if (mode == 4) {
                    float zr = 1.0f / Zv[r];
                    v0 *= zr; v1 *= zr;
                    bf h0 = __float2bfloat16(v0);
                    bf h1 = __float2bfloat16(v1);
                    *(__nv_bfloat162*)(outH + off) = __halves2bfloat162(h0, h1);
                    *(__nv_bfloat162*)(outL + off) = __halves2bfloat162(
                        __float2bfloat16(v0 - __bfloat162float(h0)),
                        __float2bfloat16(v1 - __bfloat162float(h1)));
                } else if (mode == 1) {
                    v0 += b1[c0] + b2[c0];
                    v1 += b1[c0 + 1] + b2[c0 + 1];
                    float s0 = 1.0f / (1.0f + expf(-v0));
                    float s1 = 1.0f / (1.0f + expf(-v1));
                    *(float2*)(outF + off) = make_float2(s0, s1);
                } else if (mode == 2) {
                    v0 += b1[c0] + b2[c0];
                    v1 += b1[c0 + 1] + b2[c0 + 1];
                    float s0 = (1.0f / (1.0f + expf(-v0))) * X[off];
                    float s1 = (1.0f / (1.0f + expf(-v1))) * X[off + 1];
                    bf h0 = __float2bfloat16(s0);
                    bf h1 = __float2bfloat16(s1);
                    *(__nv_bfloat162*)(outH + off) = __halves2bfloat162(h0, h1);
                    *(__nv_bfloat162*)(outL + off) = __halves2bfloat162(
                        __float2bfloat16(s0 - __bfloat162float(h0)),
                        __float2bfloat16(s1 - __bfloat162float(h1)));
                } else {
                    v0 += b1[c0] + b2[c0];
                    v1 += b1[c0 + 1] + b2[c0 + 1];
                    float t0 = tanhf(v0), t1 = tanhf(v1);
                    float u0 = U[off], u1 = U[off + 1];
                    float x0 = X[off], x1 = X[off + 1];
                    *(float2*)(outF + off) =
                        make_float2(x0 + u0 * (t0 - x0), x1 + u1 * (t1 - x1));
                }
            }
        }
    }
}

// ---------------- launch ----------------
extern "C" void kernel_launch(void* const* d_in, const int* in_sizes, int n_in,
                              void* d_out, int out_size)
{
    const float* inputs = (const float*)d_in[0];
    const float* adj    = (const float*)d_in[1];
    const float* W_fc   = (const float*)d_in[2];
    const float* b_fc   = (const float*)d_in[3];
    const float* w_q    = (const float*)d_in[4];
    const float* b_q    = (const float*)d_in[5];
    const float* w_k    = (const float*)d_in[6];
    const float* b_k    = (const float*)d_in[7];
    const float* W_uy   = (const float*)d_in[8];
    const float* b_uy   = (const float*)d_in[9];
    const float* W_ux   = (const float*)d_in[10];
    const float* b_ux   = (const float*)d_in[11];
    const float* W_ry   = (const float*)d_in[12];
    const float* b_ry   = (const float*)d_in[13];
    const float* W_rx   = (const float*)d_in[14];
    const float* b_rx   = (const float*)d_in[15];
    const float* W_ty   = (const float*)d_in[16];
    const float* b_ty   = (const float*)d_in[17];
    const float* W_tx   = (const float*)d_in[18];
    const float* b_tx   = (const float*)d_in[19];
    float* out = (float*)d_out;

    bf *in_hi, *in_lo, *fpT_hi, *fpT_lo, *y_hi, *y_lo, *rx_hi, *rx_lo;
    bf *E_hi, *E_lo, *W_hi, *W_lo;
    float *fp, *u, *Z;
    cudaGetSymbolAddress((void**)&in_hi, g_in_hi);
    cudaGetSymbolAddress((void**)&in_lo, g_in_lo);
    cudaGetSymbolAddress((void**)&fp, g_fp);
    cudaGetSymbolAddress((void**)&fpT_hi, g_fpT_hi);
    cudaGetSymbolAddress((void**)&fpT_lo, g_fpT_lo);
    cudaGetSymbolAddress((void**)&y_hi, g_y_hi);
    cudaGetSymbolAddress((void**)&y_lo, g_y_lo);
    cudaGetSymbolAddress((void**)&rx_hi, g_rx_hi);
    cudaGetSymbolAddress((void**)&rx_lo, g_rx_lo);
    cudaGetSymbolAddress((void**)&u, g_u);
    cudaGetSymbolAddress((void**)&E_hi, g_E_hi);
    cudaGetSymbolAddress((void**)&E_lo, g_E_lo);
    cudaGetSymbolAddress((void**)&Z, g_Z);
    cudaGetSymbolAddress((void**)&W_hi, g_W_hi);
    cudaGetSymbolAddress((void**)&W_lo, g_W_lo);

    cudaFuncSetAttribute(mma_gemm, cudaFuncAttributeMaxDynamicSharedMemorySize, 2 * STAGE_B);

    // split inputs + weights
    const int WSZ = DD * DD;
    split_kernel<<<(MM * DD / 4 + 255) / 256, 256>>>(inputs, in_hi, in_lo, MM * DD / 4);
    const float* Ws[7] = {W_fc, W_uy, W_ux, W_ry, W_rx, W_ty, W_tx};
    for (int i = 0; i < 7; i++)
        split_kernel<<<(WSZ / 4 + 255) / 256, 256>>>(Ws[i], W_hi + (size_t)i * WSZ,
                                                     W_lo + (size_t)i * WSZ, WSZ / 4);
    bf* Wfc_h = W_hi;                 bf* Wfc_l = W_lo;
    bf* Wuy_h = W_hi + (size_t)1*WSZ; bf* Wuy_l = W_lo + (size_t)1*WSZ;
    bf* Wux_h = W_hi + (size_t)2*WSZ; bf* Wux_l = W_lo + (size_t)2*WSZ;
    bf* Wry_h = W_hi + (size_t)3*WSZ; bf* Wry_l = W_lo + (size_t)3*WSZ;
    bf* Wrx_h = W_hi + (size_t)4*WSZ; bf* Wrx_l = W_lo + (size_t)4*WSZ;
    bf* Wty_h = W_hi + (size_t)5*WSZ; bf* Wty_l = W_lo + (size_t)5*WSZ;
    bf* Wtx_h = W_hi + (size_t)6*WSZ; bf* Wtx_l = W_lo + (size_t)6*WSZ;

    dim3 grid(DD / 128, MM / 128);  // (6, 128)
    size_t smem = 2 * STAGE_B;

    // 1) feat_proj (fp32 + transposed hi/lo)
    mma_gemm<<<grid, 256, smem>>>(in_hi, in_lo, Wfc_h, Wfc_l,
                                  in_hi, in_lo, Wfc_h, Wfc_l,
                                  b_fc, nullptr, nullptr, nullptr, nullptr,
                                  fp, fpT_hi, fpT_lo,
                                  DD, DD, DD, DD, 0, 0);
    // 2) q, k
    qk_kernel<<<MM, 256>>>(w_q, b_q, w_k, b_k);
    // 3) E, Z
    maskexp_kernel<<<MM, 256>>>(adj);
    // 4) y = (E @ fpT) / Z  (batched B)
    mma_gemm<<<grid, 256, smem>>>(E_hi, E_lo, fpT_hi, fpT_lo,
                                  E_hi, E_lo, fpT_hi, fpT_lo,
                                  nullptr, nullptr, nullptr, nullptr, Z,
                                  nullptr, y_hi, y_lo,
                                  NN, NN, NN, NN, (size_t)DD * NN, 4);
    // 5) u
    mma_gemm<<<grid, 256, smem>>>(y_hi, y_lo, Wuy_h, Wuy_l,
                                  in_hi, in_lo, Wux_h, Wux_l,
                                  b_uy, b_ux, nullptr, nullptr, nullptr,
                                  u, nullptr, nullptr,
                                  2 * DD, DD, DD, DD, 0, 1);
    // 6) rx = sigmoid(...) * inputs
    mma_gemm<<<grid, 256, smem>>>(y_hi, y_lo, Wry_h, Wry_l,
                                  in_hi, in_lo, Wrx_h, Wrx_l,
                                  b_ry, b_rx, inputs, nullptr, nullptr,
                                  nullptr, rx_hi, rx_lo,
                                  2 * DD, DD, DD, DD, 0, 2);
    // 7) out
    mma_gemm<<<grid, 256, smem>>>(y_hi, y_lo, Wty_h, Wty_l,
                                  rx_hi, rx_lo, Wtx_h, Wtx_l,
                                  b_ty, b_tx, inputs, u, nullptr,
                                  out, nullptr, nullptr,
                                  2 * DD, DD, DD, DD, 0, 3);
}

// round 6
// speedup vs baseline: 4.5919x; 1.9037x over previous
#include <cuda_runtime.h>
#include <cuda_bf16.h>
#include <cuda_fp16.h>
#include <cstdint>
#include <math.h>

#define NB 16
#define NN 1024
#define DD 768
#define MM (NB * NN)

typedef __nv_bfloat16 bf;

// ---------------- scratch ----------------
__device__ bf     g_in_hi[(size_t)MM * DD], g_in_lo[(size_t)MM * DD];
__device__ __half g_in_h[(size_t)MM * DD];
__device__ bf     g_Wfc_hi[(size_t)DD * DD], g_Wfc_lo[(size_t)DD * DD];
__device__ __half g_W6[(size_t)6 * DD * DD];
__device__ __half g_fpT[(size_t)NB * DD * NN];
__device__ __half g_y[(size_t)MM * DD];
__device__ __half g_rx[(size_t)MM * DD];
__device__ float  g_u[(size_t)MM * DD];
__device__ __half g_E[(size_t)NB * NN * NN];
__device__ float  g_Z[MM];
__device__ float  g_q[MM], g_k[MM];
__device__ float  g_vq[DD], g_vk[DD], g_cqk[2];

// ---------------- fp32 -> (hi,lo) bf16 split ----------------
__global__ __launch_bounds__(256) void split_bf_kernel(
    const float* __restrict__ src, bf* __restrict__ hi, bf* __restrict__ lo, int n4)
{
    int i = blockIdx.x * 256 + threadIdx.x;
    if (i >= n4) return;
    float4 v = ((const float4*)src)[i];
    float x[4] = {v.x, v.y, v.z, v.w};
    __nv_bfloat162 ph[2], pl[2];
#pragma unroll
    for (int p = 0; p < 2; p++) {
        bf h0 = __float2bfloat16(x[p * 2]);
        bf h1 = __float2bfloat16(x[p * 2 + 1]);
        bf l0 = __float2bfloat16(x[p * 2] - __bfloat162float(h0));
        bf l1 = __float2bfloat16(x[p * 2 + 1] - __bfloat162float(h1));
        ph[p] = __halves2bfloat162(h0, h1);
        pl[p] = __halves2bfloat162(l0, l1);
    }
    ((__nv_bfloat162*)hi)[i * 2]     = ph[0];
    ((__nv_bfloat162*)hi)[i * 2 + 1] = ph[1];
    ((__nv_bfloat162*)lo)[i * 2]     = pl[0];
    ((__nv_bfloat162*)lo)[i * 2 + 1] = pl[1];
}

// ---------------- fp32 -> fp16 convert ----------------
__global__ __launch_bounds__(256) void cvt_h_kernel(
    const float* __restrict__ src, __half* __restrict__ dst, int n4)
{
    int i = blockIdx.x * 256 + threadIdx.x;
    if (i >= n4) return;
    float4 v = ((const float4*)src)[i];
    __half2 a = __floats2half2_rn(v.x, v.y);
    __half2 b = __floats2half2_rn(v.z, v.w);
    ((__half2*)dst)[i * 2]     = a;
    ((__half2*)dst)[i * 2 + 1] = b;
}

// ---------------- vq = W_fc^T wq, vk = W_fc^T wk ----------------
__global__ __launch_bounds__(256) void vqk_kernel(
    const float* __restrict__ W_fc, const float* __restrict__ wq,
    const float* __restrict__ wk)
{
    int d = blockIdx.x * 256 + threadIdx.x;
    if (d >= DD) return;
    float sq = 0.0f, sk = 0.0f;
    for (int e = 0; e < DD; e++) {
        float w = W_fc[(size_t)e * DD + d];
        sq = fmaf(wq[e], w, sq);
        sk = fmaf(wk[e], w, sk);
    }
    g_vq[d] = sq;
    g_vk[d] = sk;
}

__global__ __launch_bounds__(256) void cqk_kernel(
    const float* __restrict__ b_fc, const float* __restrict__ wq,
    const float* __restrict__ bq, const float* __restrict__ wk,
    const float* __restrict__ bk)
{
    int tid = threadIdx.x;
    float sq = 0.0f, sk = 0.0f;
    for (int e = tid; e < DD; e += 256) {
        float b = b_fc[e];
        sq = fmaf(wq[e], b, sq);
        sk = fmaf(wk[e], b, sk);
    }
#pragma unroll
    for (int o = 16; o; o >>= 1) {
        sq += __shfl_down_sync(0xFFFFFFFFu, sq, o);
        sk += __shfl_down_sync(0xFFFFFFFFu, sk, o);
    }
    __shared__ float rq[8], rk[8];
    if ((tid & 31) == 0) { rq[tid >> 5] = sq; rk[tid >> 5] = sk; }
    __syncthreads();
    if (tid == 0) {
        float a = 0.0f, c = 0.0f;
#pragma unroll
        for (int w = 0; w < 8; w++) { a += rq[w]; c += rk[w]; }
        g_cqk[0] = a + bq[0];
        g_cqk[1] = c + bk[0];
    }
}

// ---------------- q/k per-row dots (exact, from raw inputs) ----------------
__global__ __launch_bounds__(256) void qk_kernel(const float* __restrict__ inputs)
{
    const int m = blockIdx.x;
    const float* row = inputs + (size_t)m * DD;
    const int tid = threadIdx.x;
    float sq = 0.0f, sk = 0.0f;
    for (int d = tid; d < DD; d += 256) {
        float v = row[d];
        sq = fmaf(v, g_vq[d], sq);
        sk = fmaf(v, g_vk[d], sk);
    }
#pragma unroll
    for (int o = 16; o; o >>= 1) {
        sq += __shfl_down_sync(0xFFFFFFFFu, sq, o);
        sk += __shfl_down_sync(0xFFFFFFFFu, sk, o);
    }
    __shared__ float rq[8], rk[8];
    if ((tid & 31) == 0) { rq[tid >> 5] = sq; rk[tid >> 5] = sk; }
    __syncthreads();
    if (tid == 0) {
        float a = 0.0f, c = 0.0f;
#pragma unroll
        for (int w = 0; w < 8; w++) { a += rq[w]; c += rk[w]; }
        g_q[m] = a + g_cqk[0];
        g_k[m] = c + g_cqk[1];
    }
}

// ---------------- E = adj * exp(lrelu(q+k)) fp16 + exact row sums ----------------
__global__ __launch_bounds__(256) void maskexp_kernel(const float* __restrict__ adj)
{
    const int row = blockIdx.x;
    const int b = row >> 10;
    const float qi = g_q[row];
    const float* arow = adj + (size_t)row * NN;
    const float* kb = g_k + b * NN;
    __half* er = g_E + (size_t)row * NN;

    float s = 0.0f;
    for (int j = threadIdx.x; j < NN; j += 256) {
        float a = arow[j];
        float v = qi + kb[j];
        float lr = v >= 0.0f ? v : 0.01f * v;
        float e = (a > 0.5f) ? expf(lr) : 0.0f;
        s += e;
        er[j] = __float2half(e);
    }
#pragma unroll
    for (int o = 16; o; o >>= 1) s += __shfl_down_sync(0xFFFFFFFFu, s, o);
    __shared__ float red[8];
    if ((threadIdx.x & 31) == 0) red[threadIdx.x >> 5] = s;
    __syncthreads();
    if (threadIdx.x == 0) {
        float t = 0.0f;
#pragma unroll
        for (int w = 0; w < 8; w++) t += red[w];
        g_Z[row] = t;
    }
}

// ================= MMA GEMM, templated on pass count =================
// P==3: bf16 split precision (hi*hi + hi*lo + lo*hi)
// P==1: fp16 single pass
// C[m,n] = sum_k A[m,k] * B[n,k]; BM=BN=128, BK=64, 2-stage cp.async.
// modes: 0 = v+b1 -> fpT fp16 transposed [b][n][j] (coalesced via smem transpose)
//        1 = sigmoid(v+b1+b2)          -> outF fp32
//        2 = sigmoid(v+b1+b2)*X        -> outH fp16
//        3 = (1-U)*X + U*tanh(v+b1+b2) -> outF fp32
//        4 = v / Z[m]                  -> outH fp16
#define TILE_B 16384

__device__ __forceinline__ uint32_t sw_off(int r, int c) {
    return (uint32_t)(r * 128 + ((c ^ (r & 7)) << 4));
}

__device__ __forceinline__ void ldsm4(uint32_t addr, uint32_t& r0, uint32_t& r1,
                                      uint32_t& r2, uint32_t& r3) {
    asm volatile("ldmatrix.sync.aligned.m8n8.x4.shared.b16 {%0,%1,%2,%3}, [%4];"
                 : "=r"(r0), "=r"(r1), "=r"(r2), "=r"(r3) : "r"(addr));
}

template<int P>
__device__ __forceinline__ void mma16(float* c, const uint32_t* a, const uint32_t* b) {
    if constexpr (P == 3) {
        asm volatile(
            "mma.sync.aligned.m16n8k16.row.col.f32.bf16.bf16.f32 "
            "{%0,%1,%2,%3}, {%4,%5,%6,%7}, {%8,%9}, {%0,%1,%2,%3};"
            : "+f"(c[0]), "+f"(c[1]), "+f"(c[2]), "+f"(c[3])
            : "r"(a[0]), "r"(a[1]), "r"(a[2]), "r"(a[3]), "r"(b[0]), "r"(b[1]));
    } else {
        asm volatile(
            "mma.sync.aligned.m16n8k16.row.col.f32.f16.f16.f32 "
            "{%0,%1,%2,%3}, {%4,%5,%6,%7}, {%8,%9}, {%0,%1,%2,%3};"
            : "+f"(c[0]), "+f"(c[1]), "+f"(c[2]), "+f"(c[3])
            : "r"(a[0]), "r"(a[1]), "r"(a[2]), "r"(a[3]), "r"(b[0]), "r"(b[1]));
    }
}

__device__ __forceinline__ void cp16(char* smem_dst, const void* gsrc) {
    uint32_t s = (uint32_t)__cvta_generic_to_shared(smem_dst);
    asm volatile("cp.async.cg.shared.global [%0], [%1], 16;" :: "r"(s), "l"(gsrc));
}

template<int P>
__global__ __launch_bounds__(256) void mma_gemm(
    const uint16_t* __restrict__ A1h, const uint16_t* __restrict__ A1l,
    const uint16_t* __restrict__ B1h, const uint16_t* __restrict__ B1l,
    const uint16_t* __restrict__ A2h, const uint16_t* __restrict__ A2l,
    const uint16_t* __restrict__ B2h, const uint16_t* __restrict__ B2l,
    const float* __restrict__ b1, const float* __restrict__ b2,
    const float* __restrict__ X, const float* __restrict__ U,
    const float* __restrict__ Zv,
    float* __restrict__ outF, __half* __restrict__ outH,
    int K, int K1, int lda, int ldb, size_t bstrideB, int mode)
{
    constexpr int NTILES = (P == 3) ? 4 : 2;    // A_hi[,A_lo],B_hi[,B_lo]
    constexpr int STAGE = NTILES * TILE_B;
    constexpr int BOFF = (P == 3) ? 2 * TILE_B : TILE_B;  // B_hi offset in stage
    extern __shared__ char smem[];

    const int tid = threadIdx.x;
    const int lane = tid & 31;
    const int warp = tid >> 5;
    const int wy = warp >> 1;          // 0..3
    const int wx = warp & 1;           // 0..1
    const int m0 = blockIdx.y * 128;
    const int n0 = blockIdx.x * 128;

    const size_t bOffB = (size_t)(m0 >> 10) * bstrideB;

    const int lr = tid >> 1;
    const int lc4 = (tid & 1) * 4;

    float acc[2][8][4];
#pragma unroll
    for (int mt = 0; mt < 2; mt++)
#pragma unroll
        for (int nt = 0; nt < 8; nt++)
#pragma unroll
            for (int v = 0; v < 4; v++) acc[mt][nt][v] = 0.0f;

    const int NT = K / 64;

    auto load_tile = [&](int kt, int st) {
        int kb = kt * 64;
        const uint16_t *Ah, *Al, *Bh, *Bl;
        int ko;
        if (kb < K1) { Ah = A1h; Al = A1l; Bh = B1h; Bl = B1l; ko = kb; }
        else         { Ah = A2h; Al = A2l; Bh = B2h; Bl = B2l; ko = kb - K1; }
        char* base = smem + st * STAGE;
        size_t abase = (size_t)(m0 + lr) * lda + ko;
        size_t bbase = bOffB + (size_t)(n0 + lr) * ldb + ko;
#pragma unroll
        for (int c = 0; c < 4; c++) {
            int ch = lc4 + c;
            uint32_t so = sw_off(lr, ch);
            cp16(base + so,        Ah + abase + ch * 8);
            cp16(base + BOFF + so, Bh + bbase + ch * 8);
            if constexpr (P == 3) {
                cp16(base + TILE_B + so,     Al + abase + ch * 8);
                cp16(base + 3 * TILE_B + so, Bl + bbase + ch * 8);
            }
        }
    };

    load_tile(0, 0);
    asm volatile("cp.async.commit_group;");

    for (int kt = 0; kt < NT; kt++) {
        if (kt + 1 < NT) load_tile(kt + 1, (kt + 1) & 1);
        asm volatile("cp.async.commit_group;");
        asm volatile("cp.async.wait_group 1;");
        __syncthreads();

        char* As_hi = smem + (kt & 1) * STAGE;
        char* Bs_hi = As_hi + BOFF;
        char* As_lo = As_hi + TILE_B;
        char* Bs_lo = As_hi + 3 * TILE_B;

#pragma unroll
        for (int ks = 0; ks < 4; ks++) {
            uint32_t ah[2][4], bh[8][2];
            uint32_t al[2][4], blo[8][2];
#pragma unroll
            for (int mt = 0; mt < 2; mt++) {
                int r = wy * 32 + mt * 16 + (lane & 15);
                int ch = ks * 2 + (lane >> 4);
                uint32_t so = sw_off(r, ch);
                ldsm4((uint32_t)__cvta_generic_to_shared(As_hi + so),
                      ah[mt][0], ah[mt][1], ah[mt][2], ah[mt][3]);
                if constexpr (P == 3)
                    ldsm4((uint32_t)__cvta_generic_to_shared(As_lo + so),
                          al[mt][0], al[mt][1], al[mt][2], al[mt][3]);
            }
#pragma unroll
            for (int np = 0; np < 4; np++) {
                int r = wx * 64 + np * 16 + (lane & 7) + ((lane >> 4) << 3);
                int ch = ks * 2 + ((lane >> 3) & 1);
                uint32_t so = sw_off(r, ch);
                ldsm4((uint32_t)__cvta_generic_to_shared(Bs_hi + so),
                      bh[np * 2][0], bh[np * 2][1], bh[np * 2 + 1][0], bh[np * 2 + 1][1]);
                if constexpr (P == 3)
                    ldsm4((uint32_t)__cvta_generic_to_shared(Bs_lo + so),
                          blo[np * 2][0], blo[np * 2][1], blo[np * 2 + 1][0], blo[np * 2 + 1][1]);
            }
#pragma unroll
            for (int mt = 0; mt < 2; mt++)
#pragma unroll
                for (int nt = 0; nt < 8; nt++)
                    mma16<P>(acc[mt][nt], ah[mt], bh[nt]);
            if constexpr (P == 3) {
#pragma unroll
                for (int mt = 0; mt < 2; mt++)
#pragma unroll
                    for (int nt = 0; nt < 8; nt++)
                        mma16<P>(acc[mt][nt], ah[mt], blo[nt]);
#pragma unroll
                for (int mt = 0; mt < 2; mt++)
#pragma unroll
                    for (int nt = 0; nt < 8; nt++)
                        mma16<P>(acc[mt][nt], al[mt], bh[nt]);
            }
        }
        __syncthreads();
    }

    // ---------------- epilogue ----------------
    if (mode == 0) {
        // transposed fp16 store: fpT[b][d][j], coalesced via per-warp smem transpose
        __half* T = (__half*)smem + warp * (64 * 34);
#pragma unroll
        for (int mt = 0; mt < 2; mt++) {
#pragma unroll
            for (int nt = 0; nt < 8; nt++) {
                int c0l = nt * 8 + (lane & 3) * 2;        // warp-local col 0..63
                int cg = n0 + wx * 64 + c0l;              // global col
                float* ac = acc[mt][nt];
#pragma unroll
                for (int h = 0; h < 2; h++) {
                    int rr = mt * 16 + (lane >> 2) + h * 8;  // warp-local row 0..31
                    T[c0l * 34 + rr]       = __float2half(ac[h * 2]     + b1[cg]);
                    T[(c0l + 1) * 34 + rr] = __float2half(ac[h * 2 + 1] + b1[cg + 1]);
                }
            }
        }
        __syncwarp();
        const int bb = m0 >> 10;
        const int jj0 = (m0 & 1023) + wy * 32;
#pragma unroll
        for (int cp = 0; cp < 2; cp++) {
            int c = lane + cp * 32;
            const uint32_t* src = (const uint32_t*)(T + c * 34);
            uint32_t w4[16];
#pragma unroll
            for (int i = 0; i < 16; i++) w4[i] = src[i];
            size_t g = ((size_t)bb * DD + (n0 + wx * 64 + c)) * NN + jj0;
            uint4* dst = (uint4*)(outH + g);
            dst[0] = make_uint4(w4[0],  w4[1],  w4[2],  w4[3]);
            dst[1] = make_uint4(w4[4],  w4[5],  w4[6],  w4[7]);
            dst[2] = make_uint4(w4[8],  w4[9],  w4[10], w4[11]);
            dst[3] = make_uint4(w4[12], w4[13], w4[14], w4[15]);
        }
        return;
    }

    const int mbase = m0 + wy * 32;
    const int nbase = n0 + wx * 64;
#pragma unroll
    for (int mt = 0; mt < 2; mt++) {
#pragma unroll
        for (int nt = 0; nt < 8; nt++) {
            int c0 = nbase + nt * 8 + (lane & 3) * 2;
            int r0 = mbase + mt * 16 + (lane >> 2);
            float* ac = acc[mt][nt];
#pragma unroll
            for (int h = 0; h < 2; h++) {
                int r = r0 + h * 8;
                float v0 = ac[h * 2], v1 = ac[h * 2 + 1];
                size_t off = (size_t)r * DD + c0;
                if (mode == 4) {
                    float zr = 1.0f / Zv[r];
                    *(__half2*)(outH + off) = __floats2half2_rn(v0 * zr, v1 * zr);
                } else if (mode == 1) {
                    v0 += b1[c0] + b2[c0];
                    v1 += b1[c0 + 1] + b2[c0 + 1];
                    float s0 = 1.0f / (1.0f + expf(-v0));
                    float s1 = 1.0f / (1.0f + expf(-v1));
                    *(float2*)(outF + off) = make_float2(s0, s1);
                } else if (mode == 2) {
                    v0 += b1[c0] + b2[c0];
                    v1 += b1[c0 + 1] + b2[c0 + 1];
                    float s0 = (1.0f / (1.0f + expf(-v0))) * X[off];
                    float s1 = (1.0f / (1.0f + expf(-v1))) * X[off + 1];
                    *(__half2*)(outH + off) = __floats2half2_rn(s0, s1);
                } else {
                    v0 += b1[c0] + b2[c0];
                    v1 += b1[c0 + 1] + b2[c0 + 1];
                    float t0 = tanhf(v0), t1 = tanhf(v1);
                    float u0 = U[off], u1 = U[off + 1];
                    float x0 = X[off], x1 = X[off + 1];
                    *(float2*)(outF + off) =
                        make_float2(x0 + u0 * (t0 - x0), x1 + u1 * (t1 - x1));
                }
            }
        }
    }
}

// ---------------- launch ----------------
extern "C" void kernel_launch(void* const* d_in, const int* in_sizes, int n_in,
                              void* d_out, int out_size)
{
    const float* inputs = (const float*)d_in[0];
    const float* adj    = (const float*)d_in[1];
    const float* W_fc   = (const float*)d_in[2];
    const float* b_fc   = (const float*)d_in[3];
    const float* w_q    = (const float*)d_in[4];
    const float* b_q    = (const float*)d_in[5];
    const float* w_k    = (const float*)d_in[6];
    const float* b_k    = (const float*)d_in[7];
    const float* W_uy   = (const float*)d_in[8];
    const float* b_uy   = (const float*)d_in[9];
    const float* W_ux   = (const float*)d_in[10];
    const float* b_ux   = (const float*)d_in[11];
    const float* W_ry   = (const float*)d_in[12];
    const float* b_ry   = (const float*)d_in[13];
    const float* W_rx   = (const float*)d_in[14];
    const float* b_rx   = (const float*)d_in[15];
    const float* W_ty   = (const float*)d_in[16];
    const float* b_ty   = (const float*)d_in[17];
    const float* W_tx   = (const float*)d_in[18];
    const float* b_tx   = (const float*)d_in[19];
    float* out = (float*)d_out;

    bf *in_hi, *in_lo, *Wfc_hi, *Wfc_lo;
    __half *in_h, *W6, *fpT, *y, *rx, *E;
    float *u, *Z;
    cudaGetSymbolAddress((void**)&in_hi, g_in_hi);
    cudaGetSymbolAddress((void**)&in_lo, g_in_lo);
    cudaGetSymbolAddress((void**)&in_h, g_in_h);
    cudaGetSymbolAddress((void**)&Wfc_hi, g_Wfc_hi);
    cudaGetSymbolAddress((void**)&Wfc_lo, g_Wfc_lo);
    cudaGetSymbolAddress((void**)&W6, g_W6);
    cudaGetSymbolAddress((void**)&fpT, g_fpT);
    cudaGetSymbolAddress((void**)&y, g_y);
    cudaGetSymbolAddress((void**)&rx, g_rx);
    cudaGetSymbolAddress((void**)&u, g_u);
    cudaGetSymbolAddress((void**)&E, g_E);
    cudaGetSymbolAddress((void**)&Z, g_Z);

    const int WSZ = DD * DD;
    const size_t smem3 = 2 * 4 * TILE_B;   // 128KB
    const size_t smem1 = 2 * 2 * TILE_B;   // 64KB
    cudaFuncSetAttribute(mma_gemm<3>, cudaFuncAttributeMaxDynamicSharedMemorySize, (int)smem3);
    cudaFuncSetAttribute(mma_gemm<1>, cudaFuncAttributeMaxDynamicSharedMemorySize, (int)smem1);

    // prep: splits / converts
    split_bf_kernel<<<(MM * DD / 4 + 255) / 256, 256>>>(inputs, in_hi, in_lo, MM * DD / 4);
    split_bf_kernel<<<(WSZ / 4 + 255) / 256, 256>>>(W_fc, Wfc_hi, Wfc_lo, WSZ / 4);
    cvt_h_kernel<<<(MM * DD / 4 + 255) / 256, 256>>>(inputs, in_h, MM * DD / 4);
    const float* Wg[6] = {W_uy, W_ux, W_ry, W_rx, W_ty, W_tx};
    for (int i = 0; i < 6; i++)
        cvt_h_kernel<<<(WSZ / 4 + 255) / 256, 256>>>(Wg[i], W6 + (size_t)i * WSZ, WSZ / 4);
    __half* Wuy_h = W6;
    __half* Wux_h = W6 + (size_t)1 * WSZ;
    __half* Wry_h = W6 + (size_t)2 * WSZ;
    __half* Wrx_h = W6 + (size_t)3 * WSZ;
    __half* Wty_h = W6 + (size_t)4 * WSZ;
    __half* Wtx_h = W6 + (size_t)5 * WSZ;

    // q/k path (exact fp32, independent of GEMM1)
    vqk_kernel<<<3, 256>>>(W_fc, w_q, w_k);
    cqk_kernel<<<1, 256>>>(b_fc, w_q, b_q, w_k, b_k);
    qk_kernel<<<MM, 256>>>(inputs);
    maskexp_kernel<<<MM, 256>>>(adj);

    dim3 grid(DD / 128, MM / 128);  // (6, 128)

    // 1) feat_proj (3-pass bf16) -> fpT fp16 transposed
    mma_gemm<3><<<grid, 256, smem3>>>(
        (const uint16_t*)in_hi, (const uint16_t*)in_lo,
        (const uint16_t*)Wfc_hi, (const uint16_t*)Wfc_lo,
        (const uint16_t*)in_hi, (const uint16_t*)in_lo,
        (const uint16_t*)Wfc_hi, (const uint16_t*)Wfc_lo,
        b_fc, nullptr, nullptr, nullptr, nullptr,
        nullptr, fpT, DD, DD, DD, DD, 0, 0);
    // 2) y = (E @ fpT^T)/Z   (1-pass fp16, batched B)
    mma_gemm<1><<<grid, 256, smem1>>>(
        (const uint16_t*)E, nullptr, (const uint16_t*)fpT, nullptr,
        (const uint16_t*)E, nullptr, (const uint16_t*)fpT, nullptr,
        nullptr, nullptr, nullptr, nullptr, Z,
        nullptr, y, NN, NN, NN, NN, (size_t)DD * NN, 4);
    // 3) u (1-pass fp16)
    mma_gemm<1><<<grid, 256, smem1>>>(
        (const uint16_t*)y, nullptr, (const uint16_t*)Wuy_h, nullptr,
        (const uint16_t*)in_h, nullptr, (const uint16_t*)Wux_h, nullptr,
        b_uy, b_ux, nullptr, nullptr, nullptr,
        u, nullptr, 2 * DD, DD, DD, DD, 0, 1);
    // 4) rx = sigmoid(...) * inputs (1-pass fp16)
    mma_gemm<1><<<grid, 256, smem1>>>(
        (const uint16_t*)y, nullptr, (const uint16_t*)Wry_h, nullptr,
        (const uint16_t*)in_h, nullptr, (const uint16_t*)Wrx_h, nullptr,
        b_ry, b_rx, inputs, nullptr, nullptr,
        nullptr, rx, 2 * DD, DD, DD, DD, 0, 2);
    // 5) out (1-pass fp16)
    mma_gemm<1><<<grid, 256, smem1>>>(
        (const uint16_t*)y, nullptr, (const uint16_t*)Wty_h, nullptr,
        (const uint16_t*)rx, nullptr, (const uint16_t*)Wtx_h, nullptr,
        b_ty, b_tx, inputs, u, nullptr,
        out, nullptr, 2 * DD, DD, DD, DD, 0, 3);
}

// round 7
// speedup vs baseline: 5.5056x; 1.1990x over previous
#include <cuda_runtime.h>
#include <cuda_fp16.h>
#include <cstdint>
#include <math.h>

#define NB 16
#define NN 1024
#define DD 768
#define MM (NB * NN)

// ---------------- scratch ----------------
__device__ __half g_in_h[(size_t)MM * DD];
__device__ __half g_W7[(size_t)7 * DD * DD];   // Wfc, Wuy, Wux, Wry, Wrx, Wty, Wtx
__device__ __half g_fpT[(size_t)NB * DD * NN];
__device__ __half g_y[(size_t)MM * DD];
__device__ __half g_rx[(size_t)MM * DD];
__device__ float  g_u[(size_t)MM * DD];
__device__ __half g_E[(size_t)NB * NN * NN];
__device__ float  g_Z[MM];
__device__ float  g_q[MM], g_k[MM];
__device__ float  g_vq[DD], g_vk[DD], g_cqk[2];

// ---------------- fp32 -> fp16 convert ----------------
__global__ __launch_bounds__(256) void cvt_h_kernel(
    const float* __restrict__ src, __half* __restrict__ dst, int n4)
{
    int i = blockIdx.x * 256 + threadIdx.x;
    if (i >= n4) return;
    float4 v = ((const float4*)src)[i];
    ((__half2*)dst)[i * 2]     = __floats2half2_rn(v.x, v.y);
    ((__half2*)dst)[i * 2 + 1] = __floats2half2_rn(v.z, v.w);
}

// ---------------- vq = W_fc^T wq, vk = W_fc^T wk ----------------
__global__ __launch_bounds__(256) void vqk_kernel(
    const float* __restrict__ W_fc, const float* __restrict__ wq,
    const float* __restrict__ wk)
{
    int d = blockIdx.x * 256 + threadIdx.x;
    if (d >= DD) return;
    float sq = 0.0f, sk = 0.0f;
    for (int e = 0; e < DD; e++) {
        float w = W_fc[(size_t)e * DD + d];
        sq = fmaf(wq[e], w, sq);
        sk = fmaf(wk[e], w, sk);
    }
    g_vq[d] = sq;
    g_vk[d] = sk;
}

__global__ __launch_bounds__(256) void cqk_kernel(
    const float* __restrict__ b_fc, const float* __restrict__ wq,
    const float* __restrict__ bq, const float* __restrict__ wk,
    const float* __restrict__ bk)
{
    int tid = threadIdx.x;
    float sq = 0.0f, sk = 0.0f;
    for (int e = tid; e < DD; e += 256) {
        float b = b_fc[e];
        sq = fmaf(wq[e], b, sq);
        sk = fmaf(wk[e], b, sk);
    }
#pragma unroll
    for (int o = 16; o; o >>= 1) {
        sq += __shfl_down_sync(0xFFFFFFFFu, sq, o);
        sk += __shfl_down_sync(0xFFFFFFFFu, sk, o);
    }
    __shared__ float rq[8], rk[8];
    if ((tid & 31) == 0) { rq[tid >> 5] = sq; rk[tid >> 5] = sk; }
    __syncthreads();
    if (tid == 0) {
        float a = 0.0f, c = 0.0f;
#pragma unroll
        for (int w = 0; w < 8; w++) { a += rq[w]; c += rk[w]; }
        g_cqk[0] = a + bq[0];
        g_cqk[1] = c + bk[0];
    }
}

// ---------------- q/k per-row dots (exact fp32) ----------------
__global__ __launch_bounds__(256) void qk_kernel(const float* __restrict__ inputs)
{
    const int m = blockIdx.x;
    const float* row = inputs + (size_t)m * DD;
    const int tid = threadIdx.x;
    float sq = 0.0f, sk = 0.0f;
    for (int d = tid; d < DD; d += 256) {
        float v = row[d];
        sq = fmaf(v, g_vq[d], sq);
        sk = fmaf(v, g_vk[d], sk);
    }
#pragma unroll
    for (int o = 16; o; o >>= 1) {
        sq += __shfl_down_sync(0xFFFFFFFFu, sq, o);
        sk += __shfl_down_sync(0xFFFFFFFFu, sk, o);
    }
    __shared__ float rq[8], rk[8];
    if ((tid & 31) == 0) { rq[tid >> 5] = sq; rk[tid >> 5] = sk; }
    __syncthreads();
    if (tid == 0) {
        float a = 0.0f, c = 0.0f;
#pragma unroll
        for (int w = 0; w < 8; w++) { a += rq[w]; c += rk[w]; }
        g_q[m] = a + g_cqk[0];
        g_k[m] = c + g_cqk[1];
    }
}

// ---------------- E = adj * exp(lrelu(q+k)) fp16 + exact row sums ----------------
__global__ __launch_bounds__(256) void maskexp_kernel(const float* __restrict__ adj)
{
    const int row = blockIdx.x;
    const int b = row >> 10;
    const float qi = g_q[row];
    const float* arow = adj + (size_t)row * NN;
    const float* kb = g_k + b * NN;
    __half* er = g_E + (size_t)row * NN;

    float s = 0.0f;
    for (int j = threadIdx.x; j < NN; j += 256) {
        float a = arow[j];
        float v = qi + kb[j];
        float lr = v >= 0.0f ? v : 0.01f * v;
        float e = (a > 0.5f) ? expf(lr) : 0.0f;
        s += e;
        er[j] = __float2half(e);
    }
#pragma unroll
    for (int o = 16; o; o >>= 1) s += __shfl_down_sync(0xFFFFFFFFu, s, o);
    __shared__ float red[8];
    if ((threadIdx.x & 31) == 0) red[threadIdx.x >> 5] = s;
    __syncthreads();
    if (threadIdx.x == 0) {
        float t = 0.0f;
#pragma unroll
        for (int w = 0; w < 8; w++) t += red[w];
        g_Z[row] = t;
    }
}

// ================= fp16 1-pass MMA GEMM =================
// C[m,n] = sum_k A[m,k] * B[n,k]; BM=BN=128, BK=64, 2-stage cp.async, 2 CTAs/SM.
// modes: 0 = v+b1 -> fpT fp16 transposed [b][d][j] (smem transpose, coalesced)
//        1 = sigmoid(v+b1+b2)          -> outF fp32
//        2 = sigmoid(v+b1+b2)*X        -> outH fp16
//        3 = (1-U)*X + U*tanh(v+b1+b2) -> outF fp32
//        4 = v / Z[m]                  -> outH fp16
#define TILE_B 16384
#define STAGE (2 * TILE_B)

__device__ __forceinline__ uint32_t sw_off(int r, int c) {
    return (uint32_t)(r * 128 + ((c ^ (r & 7)) << 4));
}

__device__ __forceinline__ void ldsm4(uint32_t addr, uint32_t& r0, uint32_t& r1,
                                      uint32_t& r2, uint32_t& r3) {
    asm volatile("ldmatrix.sync.aligned.m8n8.x4.shared.b16 {%0,%1,%2,%3}, [%4];"
                 : "=r"(r0), "=r"(r1), "=r"(r2), "=r"(r3) : "r"(addr));
}

__device__ __forceinline__ void mma16(float* c, const uint32_t* a, const uint32_t* b) {
    asm volatile(
        "mma.sync.aligned.m16n8k16.row.col.f32.f16.f16.f32 "
        "{%0,%1,%2,%3}, {%4,%5,%6,%7}, {%8,%9}, {%0,%1,%2,%3};"
        : "+f"(c[0]), "+f"(c[1]), "+f"(c[2]), "+f"(c[3])
        : "r"(a[0]), "r"(a[1]), "r"(a[2]), "r"(a[3]), "r"(b[0]), "r"(b[1]));
}

__device__ __forceinline__ void cp16(char* smem_dst, const void* gsrc) {
    uint32_t s = (uint32_t)__cvta_generic_to_shared(smem_dst);
    asm volatile("cp.async.cg.shared.global [%0], [%1], 16;" :: "r"(s), "l"(gsrc));
}

__global__ __launch_bounds__(256, 2) void mma_gemm(
    const __half* __restrict__ A1, const __half* __restrict__ B1,
    const __half* __restrict__ A2, const __half* __restrict__ B2,
    const float* __restrict__ b1, const float* __restrict__ b2,
    const float* __restrict__ X, const float* __restrict__ U,
    const float* __restrict__ Zv,
    float* __restrict__ outF, __half* __restrict__ outH,
    int K, int K1, int lda, int ldb, size_t bstrideB, int mode)
{
    extern __shared__ char smem[];

    const int tid = threadIdx.x;
    const int lane = tid & 31;
    const int warp = tid >> 5;
    const int wy = warp >> 1;          // 0..3
    const int wx = warp & 1;           // 0..1
    const int m0 = blockIdx.y * 128;
    const int n0 = blockIdx.x * 128;

    const size_t bOffB = (size_t)(m0 >> 10) * bstrideB;

    const int lr = tid >> 1;
    const int lc4 = (tid & 1) * 4;

    float acc[2][8][4];
#pragma unroll
    for (int mt = 0; mt < 2; mt++)
#pragma unroll
        for (int nt = 0; nt < 8; nt++)
#pragma unroll
            for (int v = 0; v < 4; v++) acc[mt][nt][v] = 0.0f;

    const int NT = K / 64;

    auto load_tile = [&](int kt, int st) {
        int kb = kt * 64;
        const __half *A, *B;
        int ko;
        if (kb < K1) { A = A1; B = B1; ko = kb; }
        else         { A = A2; B = B2; ko = kb - K1; }
        char* base = smem + st * STAGE;
        size_t abase = (size_t)(m0 + lr) * lda + ko;
        size_t bbase = bOffB + (size_t)(n0 + lr) * ldb + ko;
#pragma unroll
        for (int c = 0; c < 4; c++) {
            int ch = lc4 + c;
            uint32_t so = sw_off(lr, ch);
            cp16(base + so,          A + abase + ch * 8);
            cp16(base + TILE_B + so, B + bbase + ch * 8);
        }
    };

    load_tile(0, 0);
    asm volatile("cp.async.commit_group;");

    for (int kt = 0; kt < NT; kt++) {
        if (kt + 1 < NT) load_tile(kt + 1, (kt + 1) & 1);
        asm volatile("cp.async.commit_group;");
        asm volatile("cp.async.wait_group 1;");
        __syncthreads();

        char* As = smem + (kt & 1) * STAGE;
        char* Bs = As + TILE_B;

#pragma unroll
        for (int ks = 0; ks < 4; ks++) {
            uint32_t ah[2][4], bh[8][2];
#pragma unroll
            for (int mt = 0; mt < 2; mt++) {
                int r = wy * 32 + mt * 16 + (lane & 15);
                int ch = ks * 2 + (lane >> 4);
                uint32_t so = sw_off(r, ch);
                ldsm4((uint32_t)__cvta_generic_to_shared(As + so),
                      ah[mt][0], ah[mt][1], ah[mt][2], ah[mt][3]);
            }
#pragma unroll
            for (int np = 0; np < 4; np++) {
                int r = wx * 64 + np * 16 + (lane & 7) + ((lane >> 4) << 3);
                int ch = ks * 2 + ((lane >> 3) & 1);
                uint32_t so = sw_off(r, ch);
                ldsm4((uint32_t)__cvta_generic_to_shared(Bs + so),
                      bh[np * 2][0], bh[np * 2][1], bh[np * 2 + 1][0], bh[np * 2 + 1][1]);
            }
#pragma unroll
            for (int mt = 0; mt < 2; mt++)
#pragma unroll
                for (int nt = 0; nt < 8; nt++)
                    mma16(acc[mt][nt], ah[mt], bh[nt]);
        }
        __syncthreads();
    }

    // ---------------- epilogue ----------------
    if (mode == 0) {
        // transposed fp16 store: fpT[b][d][j], coalesced via per-warp smem transpose
        __half* T = (__half*)smem + warp * (64 * 34);
#pragma unroll
        for (int mt = 0; mt < 2; mt++) {
#pragma unroll
            for (int nt = 0; nt < 8; nt++) {
                int c0l = nt * 8 + (lane & 3) * 2;
                int cg = n0 + wx * 64 + c0l;
                float* ac = acc[mt][nt];
#pragma unroll
                for (int h = 0; h < 2; h++) {
                    int rr = mt * 16 + (lane >> 2) + h * 8;
                    T[c0l * 34 + rr]       = __float2half(ac[h * 2]     + b1[cg]);
                    T[(c0l + 1) * 34 + rr] = __float2half(ac[h * 2 + 1] + b1[cg + 1]);
                }
            }
        }
        __syncwarp();
        const int bb = m0 >> 10;
        const int jj0 = (m0 & 1023) + wy * 32;
#pragma unroll
        for (int cp = 0; cp < 2; cp++) {
            int c = lane + cp * 32;
            const uint32_t* src = (const uint32_t*)(T + c * 34);
            uint32_t w4[16];
#pragma unroll
            for (int i = 0; i < 16; i++) w4[i] = src[i];
            size_t g = ((size_t)bb * DD + (n0 + wx * 64 + c)) * NN + jj0;
            uint4* dst = (uint4*)(outH + g);
            dst[0] = make_uint4(w4[0],  w4[1],  w4[2],  w4[3]);
            dst[1] = make_uint4(w4[4],  w4[5],  w4[6],  w4[7]);
            dst[2] = make_uint4(w4[8],  w4[9],  w4[10], w4[11]);
            dst[3] = make_uint4(w4[12], w4[13], w4[14], w4[15]);
        }
        return;
    }

    const int mbase = m0 + wy * 32;
    const int nbase = n0 + wx * 64;
#pragma unroll
    for (int mt = 0; mt < 2; mt++) {
#pragma unroll
        for (int nt = 0; nt < 8; nt++) {
            int c0 = nbase + nt * 8 + (lane & 3) * 2;
            int r0 = mbase + mt * 16 + (lane >> 2);
            float* ac = acc[mt][nt];
#pragma unroll
            for (int h = 0; h < 2; h++) {
                int r = r0 + h * 8;
                float v0 = ac[h * 2], v1 = ac[h * 2 + 1];
                size_t off = (size_t)r * DD + c0;
                if (mode == 4) {
                    float zr = 1.0f / Zv[r];
                    *(__half2*)(outH + off) = __floats2half2_rn(v0 * zr, v1 * zr);
                } else if (mode == 1) {
                    v0 += b1[c0] + b2[c0];
                    v1 += b1[c0 + 1] + b2[c0 + 1];
                    float s0 = 1.0f / (1.0f + expf(-v0));
                    float s1 = 1.0f / (1.0f + expf(-v1));
                    *(float2*)(outF + off) = make_float2(s0, s1);
                } else if (mode == 2) {
                    v0 += b1[c0] + b2[c0];
                    v1 += b1[c0 + 1] + b2[c0 + 1];
                    float s0 = (1.0f / (1.0f + expf(-v0))) * X[off];
                    float s1 = (1.0f / (1.0f + expf(-v1))) * X[off + 1];
                    *(__half2*)(outH + off) = __floats2half2_rn(s0, s1);
                } else {
                    v0 += b1[c0] + b2[c0];
                    v1 += b1[c0 + 1] + b2[c0 + 1];
                    float t0 = tanhf(v0), t1 = tanhf(v1);
                    float u0 = U[off], u1 = U[off + 1];
                    float x0 = X[off], x1 = X[off + 1];
                    *(float2*)(outF + off) =
                        make_float2(x0 + u0 * (t0 - x0), x1 + u1 * (t1 - x1));
                }
            }
        }
    }
}

// ---------------- launch ----------------
extern "C" void kernel_launch(void* const* d_in, const int* in_sizes, int n_in,
                              void* d_out, int out_size)
{
    const float* inputs = (const float*)d_in[0];
    const float* adj    = (const float*)d_in[1];
    const float* W_fc   = (const float*)d_in[2];
    const float* b_fc   = (const float*)d_in[3];
    const float* w_q    = (const float*)d_in[4];
    const float* b_q    = (const float*)d_in[5];
    const float* w_k    = (const float*)d_in[6];
    const float* b_k    = (const float*)d_in[7];
    const float* W_uy   = (const float*)d_in[8];
    const float* b_uy   = (const float*)d_in[9];
    const float* W_ux   = (const float*)d_in[10];
    const float* b_ux   = (const float*)d_in[11];
    const float* W_ry   = (const float*)d_in[12];
    const float* b_ry   = (const float*)d_in[13];
    const float* W_rx   = (const float*)d_in[14];
    const float* b_rx   = (const float*)d_in[15];
    const float* W_ty   = (const float*)d_in[16];
    const float* b_ty   = (const float*)d_in[17];
    const float* W_tx   = (const float*)d_in[18];
    const float* b_tx   = (const float*)d_in[19];
    float* out = (float*)d_out;

    __half *in_h, *W7, *fpT, *y, *rx, *E;
    float *u, *Z;
    cudaGetSymbolAddress((void**)&in_h, g_in_h);
    cudaGetSymbolAddress((void**)&W7, g_W7);
    cudaGetSymbolAddress((void**)&fpT, g_fpT);
    cudaGetSymbolAddress((void**)&y, g_y);
    cudaGetSymbolAddress((void**)&rx, g_rx);
    cudaGetSymbolAddress((void**)&u, g_u);
    cudaGetSymbolAddress((void**)&E, g_E);
    cudaGetSymbolAddress((void**)&Z, g_Z);

    const int WSZ = DD * DD;
    const size_t smem = 2 * STAGE;   // 64KB
    cudaFuncSetAttribute(mma_gemm, cudaFuncAttributeMaxDynamicSharedMemorySize, (int)smem);

    // prep: converts
    cvt_h_kernel<<<(MM * DD / 4 + 255) / 256, 256>>>(inputs, in_h, MM * DD / 4);
    const float* Wg[7] = {W_fc, W_uy, W_ux, W_ry, W_rx, W_ty, W_tx};
    for (int i = 0; i < 7; i++)
        cvt_h_kernel<<<(WSZ / 4 + 255) / 256, 256>>>(Wg[i], W7 + (size_t)i * WSZ, WSZ / 4);
    __half* Wfc_h = W7;
    __half* Wuy_h = W7 + (size_t)1 * WSZ;
    __half* Wux_h = W7 + (size_t)2 * WSZ;
    __half* Wry_h = W7 + (size_t)3 * WSZ;
    __half* Wrx_h = W7 + (size_t)4 * WSZ;
    __half* Wty_h = W7 + (size_t)5 * WSZ;
    __half* Wtx_h = W7 + (size_t)6 * WSZ;

    // q/k path (exact fp32)
    vqk_kernel<<<3, 256>>>(W_fc, w_q, w_k);
    cqk_kernel<<<1, 256>>>(b_fc, w_q, b_q, w_k, b_k);
    qk_kernel<<<MM, 256>>>(inputs);
    maskexp_kernel<<<MM, 256>>>(adj);

    dim3 grid(DD / 128, MM / 128);  // (6, 128)

    // 1) feat_proj -> fpT fp16 transposed
    mma_gemm<<<grid, 256, smem>>>(in_h, Wfc_h, in_h, Wfc_h,
                                  b_fc, nullptr, nullptr, nullptr, nullptr,
                                  nullptr, fpT, DD, DD, DD, DD, 0, 0);
    // 2) y = (E @ fpT^T)/Z
    mma_gemm<<<grid, 256, smem>>>(E, fpT, E, fpT,
                                  nullptr, nullptr, nullptr, nullptr, Z,
                                  nullptr, y, NN, NN, NN, NN, (size_t)DD * NN, 4);
    // 3) u
    mma_gemm<<<grid, 256, smem>>>(y, Wuy_h, in_h, Wux_h,
                                  b_uy, b_ux, nullptr, nullptr, nullptr,
                                  u, nullptr, 2 * DD, DD, DD, DD, 0, 1);
    // 4) rx = sigmoid(...) * inputs
    mma_gemm<<<grid, 256, smem>>>(y, Wry_h, in_h, Wrx_h,
                                  b_ry, b_rx, inputs, nullptr, nullptr,
                                  nullptr, rx, 2 * DD, DD, DD, DD, 0, 2);
    // 5) out
    mma_gemm<<<grid, 256, smem>>>(y, Wty_h, rx, Wtx_h,
                                  b_ty, b_tx, inputs, u, nullptr,
                                  out, nullptr, 2 * DD, DD, DD, DD, 0, 3);
}